// round 8
// baseline (speedup 1.0000x reference)
#include <cuda_runtime.h>
#include <cstdint>

#define Bsz 256
#define Tsz 128
#define Fsz 256
#define Hsz 512
#define Csz 10

// Scratch: proj/h buffers, written in place by the recurrence.
__device__ float g_buf0[Bsz * Tsz * Hsz];   // 64 MB
__device__ float g_buf1[Bsz * Tsz * Hsz];   // 64 MB

// Per-tile_m group counters (8 groups, 128B apart to avoid false sharing).
__device__ unsigned g_cnt[8 * 32];

__global__ void reset_cnt()
{
    if (threadIdx.x < 8 * 32) g_cnt[threadIdx.x] = 0u;
}

// ---------------------------------------------------------------------------
// f32x2 packed FMA helpers (Blackwell FFMA2 — only reachable via PTX).
// Accumulators are k-paired: .lo sums even-k products, .hi odd-k products.
// ---------------------------------------------------------------------------
__device__ __forceinline__ unsigned long long ffma2(
    unsigned long long a, unsigned long long b, unsigned long long c)
{
    unsigned long long d;
    asm("fma.rn.f32x2 %0, %1, %2, %3;" : "=l"(d) : "l"(a), "l"(b), "l"(c));
    return d;
}
__device__ __forceinline__ float f2sum(unsigned long long v)
{
    float lo, hi;
    asm("mov.b64 {%0, %1}, %2;" : "=f"(lo), "=f"(hi) : "l"(v));
    return lo + hi;
}

// ---------------------------------------------------------------------------
// Projection GEMM: out[m,n] = sum_k A[m,k] * Wt[n,k] + bias1[n] + bias2[n]
// M = 32768, N = 512, K in {256, 512}.
// BM=128, BN=64, BK=16, 256 threads, microtile 8 rows x 4 cols, f32x2 accs.
// ---------------------------------------------------------------------------
#define PJ_BM 128
#define PJ_BN 64
#define PJ_BK 16
#define PJ_PA 20
#define PJ_PB 20

__global__ void __launch_bounds__(256, 2) proj_gemm(
    const float* __restrict__ A, const float* __restrict__ Wt,
    const float* __restrict__ bias1, const float* __restrict__ bias2,
    float* __restrict__ out, int K)
{
    __shared__ float As[PJ_BM * PJ_PA];   // 10.24 KB
    __shared__ float Bs[PJ_BN * PJ_PB];   //  5.12 KB

    const int tid = threadIdx.x;
    const int m0 = blockIdx.y * PJ_BM;
    const int n0 = blockIdx.x * PJ_BN;
    const int tx = tid & 15;          // -> cols tx + 16c, c = 0..3
    const int ty = tid >> 4;          // -> rows ty*8 + i, i = 0..7

    const int arow = tid >> 2;        // 0..63 ; second load uses arow+64
    const int ach  = tid & 3;
    const float* apg = A + (size_t)(m0 + arow) * K + ach * 4;
    const int bcol = tid >> 2;        // 0..63
    const float* bpg = Wt + (size_t)(n0 + bcol) * K + ach * 4;

    unsigned long long acc[8][4];
#pragma unroll
    for (int i = 0; i < 8; ++i)
#pragma unroll
        for (int c = 0; c < 4; ++c) acc[i][c] = 0ull;

    float4 ra0 = *reinterpret_cast<const float4*>(apg);
    float4 ra1 = *reinterpret_cast<const float4*>(apg + (size_t)64 * K);
    float4 rb  = *reinterpret_cast<const float4*>(bpg);

    const int S = K / PJ_BK;
    for (int s = 0; s < S; ++s) {
        *reinterpret_cast<float4*>(&As[arow * PJ_PA + ach * 4])        = ra0;
        *reinterpret_cast<float4*>(&As[(arow + 64) * PJ_PA + ach * 4]) = ra1;
        *reinterpret_cast<float4*>(&Bs[bcol * PJ_PB + ach * 4])        = rb;
        __syncthreads();

        if (s + 1 < S) {
            const size_t off = (size_t)(s + 1) * PJ_BK;
            ra0 = *reinterpret_cast<const float4*>(apg + off);
            ra1 = *reinterpret_cast<const float4*>(apg + (size_t)64 * K + off);
            rb  = *reinterpret_cast<const float4*>(bpg + off);
        }

#pragma unroll
        for (int kk = 0; kk < PJ_BK; kk += 4) {
            ulonglong2 bv[4];
#pragma unroll
            for (int c = 0; c < 4; ++c)
                bv[c] = *reinterpret_cast<const ulonglong2*>(
                    &Bs[(tx + c * 16) * PJ_PB + kk]);
#pragma unroll
            for (int i = 0; i < 8; ++i) {
                ulonglong2 av = *reinterpret_cast<const ulonglong2*>(
                    &As[(ty * 8 + i) * PJ_PA + kk]);
#pragma unroll
                for (int c = 0; c < 4; ++c) {
                    acc[i][c] = ffma2(av.x, bv[c].x, acc[i][c]);
                    acc[i][c] = ffma2(av.y, bv[c].y, acc[i][c]);
                }
            }
        }
        __syncthreads();
    }

    float bb[4];
#pragma unroll
    for (int c = 0; c < 4; ++c)
        bb[c] = bias1[n0 + tx + c * 16] + bias2[n0 + tx + c * 16];

#pragma unroll
    for (int i = 0; i < 8; ++i) {
        float* orow = out + (size_t)(m0 + ty * 8 + i) * Hsz + n0 + tx;
#pragma unroll
        for (int c = 0; c < 4; ++c)
            orow[c * 16] = f2sum(acc[i][c]) + bb[c];
    }
}

// ---------------------------------------------------------------------------
// Persistent recurrence. 128 CTAs x 512 threads (16 warps/SM, all resident).
// Tile 32 batch rows x 32 hidden cols. Microtile 2 rows x 1 col (col = lane).
// W tile resident in smem for all 128 steps as WsT[col][k], pitch 516
// (bank = (4*col + k) % 32 -> conflict-free LDS.128). h_{t-1} staged to
// Ash[32][512] each step (x reads are warp-uniform -> broadcast).
// Sync: per-tile_m group counter — CTA (m,n) at step t only needs the 16
// CTAs sharing tile_m to have finished step t-1. Monotonic counters,
// zeroed by reset_cnt before each launch.
// ---------------------------------------------------------------------------
#define REC_NBLK 128
#define REC_THREADS 512
#define REC_P 516
#define REC_SMEM_BYTES ((32 * REC_P + 32 * Hsz) * 4)   // 131584 B

__global__ void __launch_bounds__(REC_THREADS) rnn_rec(
    float* __restrict__ buf, const float* __restrict__ Whh)
{
    extern __shared__ float sm[];
    float* WsT = sm;                 // [32][REC_P]
    float* Ash = sm + 32 * REC_P;    // [32][512]

    const int tid = threadIdx.x;
    const int tile_m = blockIdx.x >> 4;     // 0..7  batch rows
    const int tile_n = blockIdx.x & 15;     // 0..15 hidden cols
    const int b0 = tile_m * 32;
    const int n0 = tile_n * 32;
    unsigned* cnt = &g_cnt[tile_m * 32];

    // Load the 32 W_hh rows for this col tile once (row n of W_hh IS col n's
    // k-vector). Visible to compute via the syncthreads below.
    for (int i = tid; i < 32 * 128; i += REC_THREADS) {
        int jj = i >> 7;
        int kc = (i & 127) * 4;
        float4 v = *reinterpret_cast<const float4*>(
            Whh + (size_t)(n0 + jj) * Hsz + kc);
        *reinterpret_cast<float4*>(WsT + jj * REC_P + kc) = v;
    }

    const int j  = tid & 31;          // col within tile (= lane)
    const int r0 = (tid >> 5) * 2;    // 2 rows per thread

    // t = 0: h_0 = relu(proj_0)
    {
        float* p0 = buf + ((size_t)(b0 + r0) * Tsz + 0) * Hsz + n0 + j;
        float* p1 = buf + ((size_t)(b0 + r0 + 1) * Tsz + 0) * Hsz + n0 + j;
        *p0 = fmaxf(*p0, 0.f);
        *p1 = fmaxf(*p1, 0.f);
    }
    __threadfence();
    __syncthreads();
    if (tid == 0) atomicAdd(cnt, 1u);

    const float* wrow = WsT + j * REC_P;
    const float* x0p  = Ash + r0 * Hsz;
    const float* x1p  = x0p + Hsz;

    for (int t = 1; t < Tsz; ++t) {
        // Wait for all 16 CTAs of this row group to finish step t-1.
        if (tid == 0) {
            const unsigned target = 16u * (unsigned)t;
            while (*(volatile unsigned*)cnt < target) { }
            __threadfence();   // acquire: order h_{t-1} reads after observation
        }
        __syncthreads();

        // Stage h_{t-1} rows b0..b0+31 into smem.
        for (int i = tid; i < 32 * 128; i += REC_THREADS) {
            int rr = i >> 7;
            int c  = (i & 127) * 4;
            float4 v = *reinterpret_cast<const float4*>(
                buf + ((size_t)(b0 + rr) * Tsz + (t - 1)) * Hsz + c);
            *reinterpret_cast<float4*>(Ash + rr * Hsz + c) = v;
        }
        __syncthreads();

        unsigned long long a0 = 0ull, a0b = 0ull, a1 = 0ull, a1b = 0ull;

        // Software-pipelined k-loop: prefetch k+8 while FMA-ing k.
        ulonglong2 w0 = *reinterpret_cast<const ulonglong2*>(wrow);
        ulonglong2 w1 = *reinterpret_cast<const ulonglong2*>(wrow + 4);
        ulonglong2 p0 = *reinterpret_cast<const ulonglong2*>(x0p);
        ulonglong2 p1 = *reinterpret_cast<const ulonglong2*>(x0p + 4);
        ulonglong2 q0 = *reinterpret_cast<const ulonglong2*>(x1p);
        ulonglong2 q1 = *reinterpret_cast<const ulonglong2*>(x1p + 4);

#pragma unroll 7
        for (int k = 0; k < Hsz - 8; k += 8) {
            ulonglong2 nw0 = *reinterpret_cast<const ulonglong2*>(wrow + k + 8);
            ulonglong2 nw1 = *reinterpret_cast<const ulonglong2*>(wrow + k + 12);
            ulonglong2 np0 = *reinterpret_cast<const ulonglong2*>(x0p + k + 8);
            ulonglong2 np1 = *reinterpret_cast<const ulonglong2*>(x0p + k + 12);
            ulonglong2 nq0 = *reinterpret_cast<const ulonglong2*>(x1p + k + 8);
            ulonglong2 nq1 = *reinterpret_cast<const ulonglong2*>(x1p + k + 12);

            a0  = ffma2(p0.x, w0.x, a0);
            a0b = ffma2(p0.y, w0.y, a0b);
            a0  = ffma2(p1.x, w1.x, a0);
            a0b = ffma2(p1.y, w1.y, a0b);
            a1  = ffma2(q0.x, w0.x, a1);
            a1b = ffma2(q0.y, w0.y, a1b);
            a1  = ffma2(q1.x, w1.x, a1);
            a1b = ffma2(q1.y, w1.y, a1b);

            w0 = nw0; w1 = nw1; p0 = np0; p1 = np1; q0 = nq0; q1 = nq1;
        }
        // Final 8 k.
        a0  = ffma2(p0.x, w0.x, a0);
        a0b = ffma2(p0.y, w0.y, a0b);
        a0  = ffma2(p1.x, w1.x, a0);
        a0b = ffma2(p1.y, w1.y, a0b);
        a1  = ffma2(q0.x, w0.x, a1);
        a1b = ffma2(q0.y, w0.y, a1b);
        a1  = ffma2(q1.x, w1.x, a1);
        a1b = ffma2(q1.y, w1.y, a1b);

        // h_t = relu(proj_t + h_{t-1} @ W^T), in place.
        float* o0 = buf + ((size_t)(b0 + r0) * Tsz + t) * Hsz + n0 + j;
        float* o1 = buf + ((size_t)(b0 + r0 + 1) * Tsz + t) * Hsz + n0 + j;
        *o0 = fmaxf(*o0 + f2sum(a0) + f2sum(a0b), 0.f);
        *o1 = fmaxf(*o1 + f2sum(a1) + f2sum(a1b), 0.f);

        __threadfence();
        __syncthreads();
        if (tid == 0) atomicAdd(cnt, 1u);
    }
}

// ---------------------------------------------------------------------------
// Final FC: out[b,c] = sum_i flat[b,i] * Wfc[c,i] + bfc[c]
// 128 CTAs; each handles batch rows b and b+128 to halve W_fc traffic.
// ---------------------------------------------------------------------------
__global__ void __launch_bounds__(256) fc_kernel(
    const float* __restrict__ flat, const float* __restrict__ Wfc,
    const float* __restrict__ bfc, float* __restrict__ out)
{
    const int b = blockIdx.x;
    const float* xr0 = flat + (size_t)b * (Tsz * Hsz);
    const float* xr1 = flat + (size_t)(b + 128) * (Tsz * Hsz);

    float acc[2][Csz];
#pragma unroll
    for (int rr = 0; rr < 2; ++rr)
#pragma unroll
        for (int c = 0; c < Csz; ++c) acc[rr][c] = 0.f;

    for (int i = threadIdx.x * 4; i < Tsz * Hsz; i += 256 * 4) {
        float4 x0 = *reinterpret_cast<const float4*>(xr0 + i);
        float4 x1 = *reinterpret_cast<const float4*>(xr1 + i);
#pragma unroll
        for (int c = 0; c < Csz; ++c) {
            float4 w = *reinterpret_cast<const float4*>(
                Wfc + (size_t)c * (Tsz * Hsz) + i);
            acc[0][c] += x0.x * w.x + x0.y * w.y + x0.z * w.z + x0.w * w.w;
            acc[1][c] += x1.x * w.x + x1.y * w.y + x1.z * w.z + x1.w * w.w;
        }
    }

#pragma unroll
    for (int rr = 0; rr < 2; ++rr)
#pragma unroll
        for (int c = 0; c < Csz; ++c)
#pragma unroll
            for (int off = 16; off > 0; off >>= 1)
                acc[rr][c] += __shfl_down_sync(0xffffffffu, acc[rr][c], off);

    __shared__ float part[2][Csz][8];
    const int warp = threadIdx.x >> 5;
    const int lane = threadIdx.x & 31;
    if (lane == 0) {
#pragma unroll
        for (int rr = 0; rr < 2; ++rr)
#pragma unroll
            for (int c = 0; c < Csz; ++c) part[rr][c][warp] = acc[rr][c];
    }
    __syncthreads();
    if (threadIdx.x < 2 * Csz) {
        int rr = threadIdx.x / Csz;
        int c  = threadIdx.x % Csz;
        float s = 0.f;
#pragma unroll
        for (int w = 0; w < 8; ++w) s += part[rr][c][w];
        out[(b + rr * 128) * Csz + c] = s + bfc[c];
    }
}

// ---------------------------------------------------------------------------
// kernel_launch: reset,proj0,rec0 -> reset,proj1,rec1 -> fc (default stream)
// ---------------------------------------------------------------------------
extern "C" void kernel_launch(void* const* d_in, const int* in_sizes, int n_in,
                              void* d_out, int out_size)
{
    (void)in_sizes; (void)n_in; (void)out_size;
    const float* x     = (const float*)d_in[0];
    const float* W_ih0 = (const float*)d_in[1];
    const float* W_hh0 = (const float*)d_in[2];
    const float* b_ih0 = (const float*)d_in[3];
    const float* b_hh0 = (const float*)d_in[4];
    const float* W_ih1 = (const float*)d_in[5];
    const float* W_hh1 = (const float*)d_in[6];
    const float* b_ih1 = (const float*)d_in[7];
    const float* b_hh1 = (const float*)d_in[8];
    const float* W_fc  = (const float*)d_in[9];
    const float* b_fc  = (const float*)d_in[10];
    float* out = (float*)d_out;

    float* buf0 = nullptr;
    float* buf1 = nullptr;
    cudaGetSymbolAddress((void**)&buf0, g_buf0);
    cudaGetSymbolAddress((void**)&buf1, g_buf1);

    cudaFuncSetAttribute(rnn_rec, cudaFuncAttributeMaxDynamicSharedMemorySize,
                         REC_SMEM_BYTES);

    dim3 pgrid(Hsz / PJ_BN, (Bsz * Tsz) / PJ_BM);   // (8, 256)

    // Layer 0
    reset_cnt<<<1, 256>>>();
    proj_gemm<<<pgrid, 256>>>(x, W_ih0, b_ih0, b_hh0, buf0, Fsz);
    rnn_rec<<<REC_NBLK, REC_THREADS, REC_SMEM_BYTES>>>(buf0, W_hh0);

    // Layer 1
    reset_cnt<<<1, 256>>>();
    proj_gemm<<<pgrid, 256>>>(buf0, W_ih1, b_ih1, b_hh1, buf1, Hsz);
    rnn_rec<<<REC_NBLK, REC_THREADS, REC_SMEM_BYTES>>>(buf1, W_hh1);

    // Classifier
    fc_kernel<<<128, 256>>>(buf1, W_fc, b_fc, out);
}

// round 9
// speedup vs baseline: 1.0384x; 1.0384x over previous
#include <cuda_runtime.h>
#include <cstdint>

#define Bsz 256
#define Tsz 128
#define Fsz 256
#define Hsz 512
#define Csz 10

// Scratch: proj/h buffers, written in place by the recurrence.
__device__ float g_buf0[Bsz * Tsz * Hsz];   // 64 MB
__device__ float g_buf1[Bsz * Tsz * Hsz];   // 64 MB

// Grid-barrier state (sense-reversal; g_sense monotonic across launches,
// g_count returns to 0 after every completed barrier -> graph-replay safe).
__device__ unsigned g_count;
__device__ unsigned g_sense;

// ---------------------------------------------------------------------------
// f32x2 packed FMA helpers (Blackwell FFMA2 — only reachable via PTX).
// Accumulators are k-paired: .lo sums even-k products, .hi odd-k products.
// ---------------------------------------------------------------------------
__device__ __forceinline__ unsigned long long ffma2(
    unsigned long long a, unsigned long long b, unsigned long long c)
{
    unsigned long long d;
    asm("fma.rn.f32x2 %0, %1, %2, %3;" : "=l"(d) : "l"(a), "l"(b), "l"(c));
    return d;
}
__device__ __forceinline__ float f2sum(unsigned long long v)
{
    float lo, hi;
    asm("mov.b64 {%0, %1}, %2;" : "=f"(lo), "=f"(hi) : "l"(v));
    return lo + hi;
}

// ---------------------------------------------------------------------------
// Projection GEMM: out[m,n] = sum_k A[m,k] * Wt[n,k] + bias1[n] + bias2[n]
// M = 32768, N = 512, K = 256 (layer-0 input projection only).
// BM=128, BN=64, BK=16, 256 threads, microtile 8 rows x 4 cols, f32x2 accs.
// ---------------------------------------------------------------------------
#define PJ_BM 128
#define PJ_BN 64
#define PJ_BK 16
#define PJ_PA 20
#define PJ_PB 20

__global__ void __launch_bounds__(256, 2) proj_gemm(
    const float* __restrict__ A, const float* __restrict__ Wt,
    const float* __restrict__ bias1, const float* __restrict__ bias2,
    float* __restrict__ out, int K)
{
    __shared__ float As[PJ_BM * PJ_PA];
    __shared__ float Bs[PJ_BN * PJ_PB];

    const int tid = threadIdx.x;
    const int m0 = blockIdx.y * PJ_BM;
    const int n0 = blockIdx.x * PJ_BN;
    const int tx = tid & 15;
    const int ty = tid >> 4;

    const int arow = tid >> 2;
    const int ach  = tid & 3;
    const float* apg = A + (size_t)(m0 + arow) * K + ach * 4;
    const int bcol = tid >> 2;
    const float* bpg = Wt + (size_t)(n0 + bcol) * K + ach * 4;

    unsigned long long acc[8][4];
#pragma unroll
    for (int i = 0; i < 8; ++i)
#pragma unroll
        for (int c = 0; c < 4; ++c) acc[i][c] = 0ull;

    float4 ra0 = *reinterpret_cast<const float4*>(apg);
    float4 ra1 = *reinterpret_cast<const float4*>(apg + (size_t)64 * K);
    float4 rb  = *reinterpret_cast<const float4*>(bpg);

    const int S = K / PJ_BK;
    for (int s = 0; s < S; ++s) {
        *reinterpret_cast<float4*>(&As[arow * PJ_PA + ach * 4])        = ra0;
        *reinterpret_cast<float4*>(&As[(arow + 64) * PJ_PA + ach * 4]) = ra1;
        *reinterpret_cast<float4*>(&Bs[bcol * PJ_PB + ach * 4])        = rb;
        __syncthreads();

        if (s + 1 < S) {
            const size_t off = (size_t)(s + 1) * PJ_BK;
            ra0 = *reinterpret_cast<const float4*>(apg + off);
            ra1 = *reinterpret_cast<const float4*>(apg + (size_t)64 * K + off);
            rb  = *reinterpret_cast<const float4*>(bpg + off);
        }

#pragma unroll
        for (int kk = 0; kk < PJ_BK; kk += 4) {
            ulonglong2 bv[4];
#pragma unroll
            for (int c = 0; c < 4; ++c)
                bv[c] = *reinterpret_cast<const ulonglong2*>(
                    &Bs[(tx + c * 16) * PJ_PB + kk]);
#pragma unroll
            for (int i = 0; i < 8; ++i) {
                ulonglong2 av = *reinterpret_cast<const ulonglong2*>(
                    &As[(ty * 8 + i) * PJ_PA + kk]);
#pragma unroll
                for (int c = 0; c < 4; ++c) {
                    acc[i][c] = ffma2(av.x, bv[c].x, acc[i][c]);
                    acc[i][c] = ffma2(av.y, bv[c].y, acc[i][c]);
                }
            }
        }
        __syncthreads();
    }

    float bb[4];
#pragma unroll
    for (int c = 0; c < 4; ++c)
        bb[c] = bias1[n0 + tx + c * 16] + bias2[n0 + tx + c * 16];

#pragma unroll
    for (int i = 0; i < 8; ++i) {
        float* orow = out + (size_t)(m0 + ty * 8 + i) * Hsz + n0 + tx;
#pragma unroll
        for (int c = 0; c < 4; ++c)
            orow[c * 16] = f2sum(acc[i][c]) + bb[c];
    }
}

// ---------------------------------------------------------------------------
// Grid barrier (R7-best config: single counter + monotonic sense).
// ---------------------------------------------------------------------------
#define REC_NBLK 128
#define REC_P 516

__device__ __forceinline__ void grid_barrier(unsigned& gen)
{
    __syncthreads();
    if (threadIdx.x == 0) {
        __threadfence();   // release: publish this CTA's prior global writes
        unsigned arrived = atomicAdd(&g_count, 1u);
        gen++;
        if (arrived == REC_NBLK - 1) {
            atomicExch(&g_count, 0u);
            __threadfence();
            atomicAdd(&g_sense, 1u);
        } else {
            while ((int)(*(volatile unsigned*)&g_sense - gen) < 0) { }
        }
        __threadfence();   // acquire
    }
    __syncthreads();
}

// ---------------------------------------------------------------------------
// Fused recurrence (layer 0) + next-layer projection.
// 128 CTAs x 256 threads, persistent. Tile 32 batch rows x 32 hidden cols.
// Microtile 4 rows x 1 col (col = lane). Smem holds W_hh col-tile AND
// W_ih1 col-tile for all 128 steps, plus the Ash staging buffer.
// During step t (after staging h_{t-1}), computes BOTH
//   h_t        = relu(proj0_t + h_{t-1} @ W_hh^T)      -> buf   (in place)
//   proj1_{t-1}=       h_{t-1} @ W_ih1^T + bias        -> bufN
// off the same x loads. Epilogue step handles proj1_{127}.
// ---------------------------------------------------------------------------
#define REC0_SMEM_BYTES ((2 * 32 * REC_P + 32 * Hsz) * 4)   // 197632 B

__global__ void __launch_bounds__(256) rnn_rec0_fused(
    float* __restrict__ buf, float* __restrict__ bufN,
    const float* __restrict__ Whh, const float* __restrict__ Wih1,
    const float* __restrict__ bih1, const float* __restrict__ bhh1)
{
    extern __shared__ float sm[];
    float* WsH = sm;                     // [32][REC_P]  W_hh cols
    float* WsP = sm + 32 * REC_P;        // [32][REC_P]  W_ih1 cols
    float* Ash = sm + 2 * 32 * REC_P;    // [32][512]

    const int tid = threadIdx.x;
    const int tile_m = blockIdx.x >> 4;
    const int tile_n = blockIdx.x & 15;
    const int b0 = tile_m * 32;
    const int n0 = tile_n * 32;

    // Load both weight col-tiles once for all 128 steps.
    for (int i = tid; i < 32 * 128; i += 256) {
        int jj = i >> 7;
        int kc = (i & 127) * 4;
        float4 vh = *reinterpret_cast<const float4*>(
            Whh + (size_t)(n0 + jj) * Hsz + kc);
        *reinterpret_cast<float4*>(WsH + jj * REC_P + kc) = vh;
        float4 vp = *reinterpret_cast<const float4*>(
            Wih1 + (size_t)(n0 + jj) * Hsz + kc);
        *reinterpret_cast<float4*>(WsP + jj * REC_P + kc) = vp;
    }

    unsigned gen = 0;
    if (tid == 0) gen = *(volatile unsigned*)&g_sense;

    const int j  = tid & 31;          // col within tile (= lane)
    const int r0 = (tid >> 5) * 4;    // 4 rows per thread

    const float biasP = bih1[n0 + j] + bhh1[n0 + j];

    // t = 0: h_0 = relu(proj0_0)
#pragma unroll
    for (int i = 0; i < 4; ++i) {
        float* p = buf + ((size_t)(b0 + r0 + i) * Tsz + 0) * Hsz + n0 + j;
        *p = fmaxf(*p, 0.f);
    }
    __threadfence();

    const float* wH = WsH + j * REC_P;
    const float* wP = WsP + j * REC_P;

    for (int t = 1; t <= Tsz; ++t) {
        grid_barrier(gen);   // h_{t-1} visible everywhere; guards Ash reuse

        // Stage h_{t-1} rows b0..b0+31 into smem.
        for (int i = tid; i < 32 * 128; i += 256) {
            int rr = i >> 7;
            int c  = (i & 127) * 4;
            float4 v = *reinterpret_cast<const float4*>(
                buf + ((size_t)(b0 + rr) * Tsz + (t - 1)) * Hsz + c);
            *reinterpret_cast<float4*>(Ash + rr * Hsz + c) = v;
        }
        __syncthreads();

        unsigned long long a[4]  = {0ull, 0ull, 0ull, 0ull};   // rec even-k
        unsigned long long aB[4] = {0ull, 0ull, 0ull, 0ull};   // rec odd-k
        unsigned long long p[4]  = {0ull, 0ull, 0ull, 0ull};   // proj even-k
        unsigned long long pB[4] = {0ull, 0ull, 0ull, 0ull};   // proj odd-k

#pragma unroll 4
        for (int k = 0; k < Hsz; k += 8) {
            ulonglong2 h0 = *reinterpret_cast<const ulonglong2*>(wH + k);
            ulonglong2 h1 = *reinterpret_cast<const ulonglong2*>(wH + k + 4);
            ulonglong2 q0 = *reinterpret_cast<const ulonglong2*>(wP + k);
            ulonglong2 q1 = *reinterpret_cast<const ulonglong2*>(wP + k + 4);
#pragma unroll
            for (int i = 0; i < 4; ++i) {
                const float* xr = Ash + (r0 + i) * Hsz + k;
                ulonglong2 x0 = *reinterpret_cast<const ulonglong2*>(xr);
                ulonglong2 x1 = *reinterpret_cast<const ulonglong2*>(xr + 4);
                a[i]  = ffma2(x0.x, h0.x, a[i]);
                aB[i] = ffma2(x0.y, h0.y, aB[i]);
                a[i]  = ffma2(x1.x, h1.x, a[i]);
                aB[i] = ffma2(x1.y, h1.y, aB[i]);
                p[i]  = ffma2(x0.x, q0.x, p[i]);
                pB[i] = ffma2(x0.y, q0.y, pB[i]);
                p[i]  = ffma2(x1.x, q1.x, p[i]);
                pB[i] = ffma2(x1.y, q1.y, pB[i]);
            }
        }

        // proj1[:, t-1, :] -> bufN  (always; covers t-1 = 0..127)
#pragma unroll
        for (int i = 0; i < 4; ++i) {
            float* po = bufN + ((size_t)(b0 + r0 + i) * Tsz + (t - 1)) * Hsz + n0 + j;
            *po = f2sum(p[i]) + f2sum(pB[i]) + biasP;
        }

        // h_t = relu(proj0_t + h_{t-1} @ W_hh^T), in place (skip on epilogue).
        if (t < Tsz) {
#pragma unroll
            for (int i = 0; i < 4; ++i) {
                float* o = buf + ((size_t)(b0 + r0 + i) * Tsz + t) * Hsz + n0 + j;
                *o = fmaxf(*o + f2sum(a[i]) + f2sum(aB[i]), 0.f);
            }
        }
        // Next barrier's tid0 fence publishes these stores.
    }
}

// ---------------------------------------------------------------------------
// Plain recurrence (layer 1) — R7-best configuration.
// ---------------------------------------------------------------------------
#define REC_SMEM_BYTES ((32 * REC_P + 32 * Hsz) * 4)   // 131584 B

__global__ void __launch_bounds__(256) rnn_rec(
    float* __restrict__ buf, const float* __restrict__ Whh)
{
    extern __shared__ float sm[];
    float* WsT = sm;                 // [32][REC_P]
    float* Ash = sm + 32 * REC_P;    // [32][512]

    const int tid = threadIdx.x;
    const int tile_m = blockIdx.x >> 4;
    const int tile_n = blockIdx.x & 15;
    const int b0 = tile_m * 32;
    const int n0 = tile_n * 32;

    for (int i = tid; i < 32 * 128; i += 256) {
        int jj = i >> 7;
        int kc = (i & 127) * 4;
        float4 v = *reinterpret_cast<const float4*>(
            Whh + (size_t)(n0 + jj) * Hsz + kc);
        *reinterpret_cast<float4*>(WsT + jj * REC_P + kc) = v;
    }

    unsigned gen = 0;
    if (tid == 0) gen = *(volatile unsigned*)&g_sense;

    const int j  = tid & 31;
    const int r0 = (tid >> 5) * 4;

#pragma unroll
    for (int i = 0; i < 4; ++i) {
        float* p = buf + ((size_t)(b0 + r0 + i) * Tsz + 0) * Hsz + n0 + j;
        *p = fmaxf(*p, 0.f);
    }
    __threadfence();

    const float* wrow = WsT + j * REC_P;

    for (int t = 1; t < Tsz; ++t) {
        grid_barrier(gen);

        for (int i = tid; i < 32 * 128; i += 256) {
            int rr = i >> 7;
            int c  = (i & 127) * 4;
            float4 v = *reinterpret_cast<const float4*>(
                buf + ((size_t)(b0 + rr) * Tsz + (t - 1)) * Hsz + c);
            *reinterpret_cast<float4*>(Ash + rr * Hsz + c) = v;
        }
        __syncthreads();

        unsigned long long a[4]  = {0ull, 0ull, 0ull, 0ull};
        unsigned long long aB[4] = {0ull, 0ull, 0ull, 0ull};

#pragma unroll 4
        for (int k = 0; k < Hsz; k += 8) {
            ulonglong2 w0 = *reinterpret_cast<const ulonglong2*>(wrow + k);
            ulonglong2 w1 = *reinterpret_cast<const ulonglong2*>(wrow + k + 4);
#pragma unroll
            for (int i = 0; i < 4; ++i) {
                const float* xr = Ash + (r0 + i) * Hsz + k;
                ulonglong2 x0 = *reinterpret_cast<const ulonglong2*>(xr);
                ulonglong2 x1 = *reinterpret_cast<const ulonglong2*>(xr + 4);
                a[i]  = ffma2(x0.x, w0.x, a[i]);
                aB[i] = ffma2(x0.y, w0.y, aB[i]);
                a[i]  = ffma2(x1.x, w1.x, a[i]);
                aB[i] = ffma2(x1.y, w1.y, aB[i]);
            }
        }

#pragma unroll
        for (int i = 0; i < 4; ++i) {
            float* o = buf + ((size_t)(b0 + r0 + i) * Tsz + t) * Hsz + n0 + j;
            *o = fmaxf(*o + f2sum(a[i]) + f2sum(aB[i]), 0.f);
        }
    }
}

// ---------------------------------------------------------------------------
// Final FC: out[b,c] = sum_i flat[b,i] * Wfc[c,i] + bfc[c]
// 128 CTAs; each handles batch rows b and b+128 to halve W_fc traffic.
// ---------------------------------------------------------------------------
__global__ void __launch_bounds__(256) fc_kernel(
    const float* __restrict__ flat, const float* __restrict__ Wfc,
    const float* __restrict__ bfc, float* __restrict__ out)
{
    const int b = blockIdx.x;
    const float* xr0 = flat + (size_t)b * (Tsz * Hsz);
    const float* xr1 = flat + (size_t)(b + 128) * (Tsz * Hsz);

    float acc[2][Csz];
#pragma unroll
    for (int rr = 0; rr < 2; ++rr)
#pragma unroll
        for (int c = 0; c < Csz; ++c) acc[rr][c] = 0.f;

    for (int i = threadIdx.x * 4; i < Tsz * Hsz; i += 256 * 4) {
        float4 x0 = *reinterpret_cast<const float4*>(xr0 + i);
        float4 x1 = *reinterpret_cast<const float4*>(xr1 + i);
#pragma unroll
        for (int c = 0; c < Csz; ++c) {
            float4 w = *reinterpret_cast<const float4*>(
                Wfc + (size_t)c * (Tsz * Hsz) + i);
            acc[0][c] += x0.x * w.x + x0.y * w.y + x0.z * w.z + x0.w * w.w;
            acc[1][c] += x1.x * w.x + x1.y * w.y + x1.z * w.z + x1.w * w.w;
        }
    }

#pragma unroll
    for (int rr = 0; rr < 2; ++rr)
#pragma unroll
        for (int c = 0; c < Csz; ++c)
#pragma unroll
            for (int off = 16; off > 0; off >>= 1)
                acc[rr][c] += __shfl_down_sync(0xffffffffu, acc[rr][c], off);

    __shared__ float part[2][Csz][8];
    const int warp = threadIdx.x >> 5;
    const int lane = threadIdx.x & 31;
    if (lane == 0) {
#pragma unroll
        for (int rr = 0; rr < 2; ++rr)
#pragma unroll
            for (int c = 0; c < Csz; ++c) part[rr][c][warp] = acc[rr][c];
    }
    __syncthreads();
    if (threadIdx.x < 2 * Csz) {
        int rr = threadIdx.x / Csz;
        int c  = threadIdx.x % Csz;
        float s = 0.f;
#pragma unroll
        for (int w = 0; w < 8; ++w) s += part[rr][c][w];
        out[(b + rr * 128) * Csz + c] = s + bfc[c];
    }
}

// ---------------------------------------------------------------------------
// kernel_launch: proj0 -> rec0_fused(+proj1) -> rec1 -> fc (default stream)
// ---------------------------------------------------------------------------
extern "C" void kernel_launch(void* const* d_in, const int* in_sizes, int n_in,
                              void* d_out, int out_size)
{
    (void)in_sizes; (void)n_in; (void)out_size;
    const float* x     = (const float*)d_in[0];
    const float* W_ih0 = (const float*)d_in[1];
    const float* W_hh0 = (const float*)d_in[2];
    const float* b_ih0 = (const float*)d_in[3];
    const float* b_hh0 = (const float*)d_in[4];
    const float* W_ih1 = (const float*)d_in[5];
    const float* W_hh1 = (const float*)d_in[6];
    const float* b_ih1 = (const float*)d_in[7];
    const float* b_hh1 = (const float*)d_in[8];
    const float* W_fc  = (const float*)d_in[9];
    const float* b_fc  = (const float*)d_in[10];
    float* out = (float*)d_out;

    float* buf0 = nullptr;
    float* buf1 = nullptr;
    cudaGetSymbolAddress((void**)&buf0, g_buf0);
    cudaGetSymbolAddress((void**)&buf1, g_buf1);

    cudaFuncSetAttribute(rnn_rec0_fused,
                         cudaFuncAttributeMaxDynamicSharedMemorySize,
                         REC0_SMEM_BYTES);
    cudaFuncSetAttribute(rnn_rec,
                         cudaFuncAttributeMaxDynamicSharedMemorySize,
                         REC_SMEM_BYTES);

    dim3 pgrid(Hsz / PJ_BN, (Bsz * Tsz) / PJ_BM);   // (8, 256)

    // Layer 0 projection
    proj_gemm<<<pgrid, 256>>>(x, W_ih0, b_ih0, b_hh0, buf0, Fsz);
    // Layer 0 recurrence fused with layer 1 projection
    rnn_rec0_fused<<<REC_NBLK, 256, REC0_SMEM_BYTES>>>(
        buf0, buf1, W_hh0, W_ih1, b_ih1, b_hh1);
    // Layer 1 recurrence
    rnn_rec<<<REC_NBLK, 256, REC_SMEM_BYTES>>>(buf1, W_hh1);
    // Classifier
    fc_kernel<<<128, 256>>>(buf1, W_fc, b_fc, out);
}

// round 10
// speedup vs baseline: 1.0447x; 1.0061x over previous
#include <cuda_runtime.h>
#include <cstdint>

#define Bsz 256
#define Tsz 128
#define Fsz 256
#define Hsz 512
#define Csz 10

// Scratch: proj/h buffers, written in place by the recurrence.
__device__ float g_buf0[Bsz * Tsz * Hsz];   // 64 MB
__device__ float g_buf1[Bsz * Tsz * Hsz];   // 64 MB

// Distributed barrier: one padded flag per CTA (128B apart -> no hot line,
// no same-address atomic serialization). Flag value = last completed step+1.
#define REC_NBLK 128
__device__ unsigned g_flag[REC_NBLK * 32];

__global__ void reset_flags()
{
    if (threadIdx.x < REC_NBLK) g_flag[threadIdx.x * 32] = 0u;
}

// ---------------------------------------------------------------------------
// f32x2 packed FMA helpers (Blackwell FFMA2 — only reachable via PTX).
// ---------------------------------------------------------------------------
__device__ __forceinline__ unsigned long long ffma2(
    unsigned long long a, unsigned long long b, unsigned long long c)
{
    unsigned long long d;
    asm("fma.rn.f32x2 %0, %1, %2, %3;" : "=l"(d) : "l"(a), "l"(b), "l"(c));
    return d;
}
__device__ __forceinline__ float f2sum(unsigned long long v)
{
    float lo, hi;
    asm("mov.b64 {%0, %1}, %2;" : "=f"(lo), "=f"(hi) : "l"(v));
    return lo + hi;
}

// ---------------------------------------------------------------------------
// Projection GEMM (layer-0 input projection, K=256).
// BM=128, BN=64, BK=16, 256 threads, microtile 8 rows x 4 cols, f32x2 accs.
// ---------------------------------------------------------------------------
#define PJ_BM 128
#define PJ_BN 64
#define PJ_BK 16
#define PJ_PA 20
#define PJ_PB 20

__global__ void __launch_bounds__(256, 2) proj_gemm(
    const float* __restrict__ A, const float* __restrict__ Wt,
    const float* __restrict__ bias1, const float* __restrict__ bias2,
    float* __restrict__ out, int K)
{
    __shared__ float As[PJ_BM * PJ_PA];
    __shared__ float Bs[PJ_BN * PJ_PB];

    const int tid = threadIdx.x;
    const int m0 = blockIdx.y * PJ_BM;
    const int n0 = blockIdx.x * PJ_BN;
    const int tx = tid & 15;
    const int ty = tid >> 4;

    const int arow = tid >> 2;
    const int ach  = tid & 3;
    const float* apg = A + (size_t)(m0 + arow) * K + ach * 4;
    const int bcol = tid >> 2;
    const float* bpg = Wt + (size_t)(n0 + bcol) * K + ach * 4;

    unsigned long long acc[8][4];
#pragma unroll
    for (int i = 0; i < 8; ++i)
#pragma unroll
        for (int c = 0; c < 4; ++c) acc[i][c] = 0ull;

    float4 ra0 = *reinterpret_cast<const float4*>(apg);
    float4 ra1 = *reinterpret_cast<const float4*>(apg + (size_t)64 * K);
    float4 rb  = *reinterpret_cast<const float4*>(bpg);

    const int S = K / PJ_BK;
    for (int s = 0; s < S; ++s) {
        *reinterpret_cast<float4*>(&As[arow * PJ_PA + ach * 4])        = ra0;
        *reinterpret_cast<float4*>(&As[(arow + 64) * PJ_PA + ach * 4]) = ra1;
        *reinterpret_cast<float4*>(&Bs[bcol * PJ_PB + ach * 4])        = rb;
        __syncthreads();

        if (s + 1 < S) {
            const size_t off = (size_t)(s + 1) * PJ_BK;
            ra0 = *reinterpret_cast<const float4*>(apg + off);
            ra1 = *reinterpret_cast<const float4*>(apg + (size_t)64 * K + off);
            rb  = *reinterpret_cast<const float4*>(bpg + off);
        }

#pragma unroll
        for (int kk = 0; kk < PJ_BK; kk += 4) {
            ulonglong2 bv[4];
#pragma unroll
            for (int c = 0; c < 4; ++c)
                bv[c] = *reinterpret_cast<const ulonglong2*>(
                    &Bs[(tx + c * 16) * PJ_PB + kk]);
#pragma unroll
            for (int i = 0; i < 8; ++i) {
                ulonglong2 av = *reinterpret_cast<const ulonglong2*>(
                    &As[(ty * 8 + i) * PJ_PA + kk]);
#pragma unroll
                for (int c = 0; c < 4; ++c) {
                    acc[i][c] = ffma2(av.x, bv[c].x, acc[i][c]);
                    acc[i][c] = ffma2(av.y, bv[c].y, acc[i][c]);
                }
            }
        }
        __syncthreads();
    }

    float bb[4];
#pragma unroll
    for (int c = 0; c < 4; ++c)
        bb[c] = bias1[n0 + tx + c * 16] + bias2[n0 + tx + c * 16];

#pragma unroll
    for (int i = 0; i < 8; ++i) {
        float* orow = out + (size_t)(m0 + ty * 8 + i) * Hsz + n0 + tx;
#pragma unroll
        for (int c = 0; c < 4; ++c)
            orow[c * 16] = f2sum(acc[i][c]) + bb[c];
    }
}

// ---------------------------------------------------------------------------
// Distributed-flag barrier primitives.
// post: this CTA finished step (val-1). wait: all CTAs posted >= val.
// Writer protocol: h stores -> threadfence (release) -> flag store.
// Reader: observe flags -> threadfence (acquire) -> syncthreads -> h loads.
// L1 staleness is a non-issue: every cross-CTA h line is first-touch.
// ---------------------------------------------------------------------------
__device__ __forceinline__ void flag_post(int cta, unsigned val)
{
    __syncthreads();                 // all threads' h_t stores issued
    if (threadIdx.x == 0) {
        __threadfence();             // release
        *(volatile unsigned*)&g_flag[cta * 32] = val;
    }
}

__device__ __forceinline__ void flag_wait(unsigned val)
{
    if (threadIdx.x < REC_NBLK) {
        while (*(volatile unsigned*)&g_flag[threadIdx.x * 32] < val) { }
        __threadfence();             // acquire (per polling warp)
    }
    __syncthreads();
}

// ---------------------------------------------------------------------------
// Fused recurrence (layer 0) + next-layer projection.
// 128 CTAs x 256 threads, persistent. Tile 32 batch rows x 32 hidden cols.
// During step t (after staging h_{t-1}) computes BOTH
//   h_t         = relu(proj0_t + h_{t-1} @ W_hh^T)   -> buf  (in place)
//   proj1_{t-1} =        h_{t-1} @ W_ih1^T + bias    -> bufN
// ---------------------------------------------------------------------------
#define REC_P 516
#define REC0_SMEM_BYTES ((2 * 32 * REC_P + 32 * Hsz) * 4)   // 197632 B

__global__ void __launch_bounds__(256) rnn_rec0_fused(
    float* __restrict__ buf, float* __restrict__ bufN,
    const float* __restrict__ Whh, const float* __restrict__ Wih1,
    const float* __restrict__ bih1, const float* __restrict__ bhh1)
{
    extern __shared__ float sm[];
    float* WsH = sm;                     // [32][REC_P]  W_hh cols
    float* WsP = sm + 32 * REC_P;        // [32][REC_P]  W_ih1 cols
    float* Ash = sm + 2 * 32 * REC_P;    // [32][512]

    const int tid = threadIdx.x;
    const int cta = blockIdx.x;
    const int tile_m = cta >> 4;
    const int tile_n = cta & 15;
    const int b0 = tile_m * 32;
    const int n0 = tile_n * 32;

    for (int i = tid; i < 32 * 128; i += 256) {
        int jj = i >> 7;
        int kc = (i & 127) * 4;
        float4 vh = *reinterpret_cast<const float4*>(
            Whh + (size_t)(n0 + jj) * Hsz + kc);
        *reinterpret_cast<float4*>(WsH + jj * REC_P + kc) = vh;
        float4 vp = *reinterpret_cast<const float4*>(
            Wih1 + (size_t)(n0 + jj) * Hsz + kc);
        *reinterpret_cast<float4*>(WsP + jj * REC_P + kc) = vp;
    }

    const int j  = tid & 31;
    const int r0 = (tid >> 5) * 4;
    const float biasP = bih1[n0 + j] + bhh1[n0 + j];

    // t = 0: h_0 = relu(proj0_0)
#pragma unroll
    for (int i = 0; i < 4; ++i) {
        float* p = buf + ((size_t)(b0 + r0 + i) * Tsz + 0) * Hsz + n0 + j;
        *p = fmaxf(*p, 0.f);
    }
    flag_post(cta, 1u);

    const float* wH = WsH + j * REC_P;
    const float* wP = WsP + j * REC_P;

    for (int t = 1; t <= Tsz; ++t) {
        flag_wait((unsigned)t);   // all CTAs finished step t-1; guards Ash reuse

        for (int i = tid; i < 32 * 128; i += 256) {
            int rr = i >> 7;
            int c  = (i & 127) * 4;
            float4 v = *reinterpret_cast<const float4*>(
                buf + ((size_t)(b0 + rr) * Tsz + (t - 1)) * Hsz + c);
            *reinterpret_cast<float4*>(Ash + rr * Hsz + c) = v;
        }
        __syncthreads();

        unsigned long long a[4]  = {0ull, 0ull, 0ull, 0ull};
        unsigned long long aB[4] = {0ull, 0ull, 0ull, 0ull};
        unsigned long long p[4]  = {0ull, 0ull, 0ull, 0ull};
        unsigned long long pB[4] = {0ull, 0ull, 0ull, 0ull};

#pragma unroll 4
        for (int k = 0; k < Hsz; k += 8) {
            ulonglong2 h0 = *reinterpret_cast<const ulonglong2*>(wH + k);
            ulonglong2 h1 = *reinterpret_cast<const ulonglong2*>(wH + k + 4);
            ulonglong2 q0 = *reinterpret_cast<const ulonglong2*>(wP + k);
            ulonglong2 q1 = *reinterpret_cast<const ulonglong2*>(wP + k + 4);
#pragma unroll
            for (int i = 0; i < 4; ++i) {
                const float* xr = Ash + (r0 + i) * Hsz + k;
                ulonglong2 x0 = *reinterpret_cast<const ulonglong2*>(xr);
                ulonglong2 x1 = *reinterpret_cast<const ulonglong2*>(xr + 4);
                a[i]  = ffma2(x0.x, h0.x, a[i]);
                aB[i] = ffma2(x0.y, h0.y, aB[i]);
                a[i]  = ffma2(x1.x, h1.x, a[i]);
                aB[i] = ffma2(x1.y, h1.y, aB[i]);
                p[i]  = ffma2(x0.x, q0.x, p[i]);
                pB[i] = ffma2(x0.y, q0.y, pB[i]);
                p[i]  = ffma2(x1.x, q1.x, p[i]);
                pB[i] = ffma2(x1.y, q1.y, pB[i]);
            }
        }

        // proj1[:, t-1, :] -> bufN
#pragma unroll
        for (int i = 0; i < 4; ++i) {
            float* po = bufN + ((size_t)(b0 + r0 + i) * Tsz + (t - 1)) * Hsz + n0 + j;
            *po = f2sum(p[i]) + f2sum(pB[i]) + biasP;
        }

        // h_t = relu(proj0_t + h_{t-1} @ W_hh^T), in place (skip on epilogue)
        if (t < Tsz) {
#pragma unroll
            for (int i = 0; i < 4; ++i) {
                float* o = buf + ((size_t)(b0 + r0 + i) * Tsz + t) * Hsz + n0 + j;
                *o = fmaxf(*o + f2sum(a[i]) + f2sum(aB[i]), 0.f);
            }
            flag_post(cta, (unsigned)(t + 1));
        }
    }
}

// ---------------------------------------------------------------------------
// Plain recurrence (layer 1).
// ---------------------------------------------------------------------------
#define REC_SMEM_BYTES ((32 * REC_P + 32 * Hsz) * 4)   // 131584 B

__global__ void __launch_bounds__(256) rnn_rec(
    float* __restrict__ buf, const float* __restrict__ Whh)
{
    extern __shared__ float sm[];
    float* WsT = sm;                 // [32][REC_P]
    float* Ash = sm + 32 * REC_P;    // [32][512]

    const int tid = threadIdx.x;
    const int cta = blockIdx.x;
    const int tile_m = cta >> 4;
    const int tile_n = cta & 15;
    const int b0 = tile_m * 32;
    const int n0 = tile_n * 32;

    for (int i = tid; i < 32 * 128; i += 256) {
        int jj = i >> 7;
        int kc = (i & 127) * 4;
        float4 v = *reinterpret_cast<const float4*>(
            Whh + (size_t)(n0 + jj) * Hsz + kc);
        *reinterpret_cast<float4*>(WsT + jj * REC_P + kc) = v;
    }

    const int j  = tid & 31;
    const int r0 = (tid >> 5) * 4;

#pragma unroll
    for (int i = 0; i < 4; ++i) {
        float* p = buf + ((size_t)(b0 + r0 + i) * Tsz + 0) * Hsz + n0 + j;
        *p = fmaxf(*p, 0.f);
    }
    flag_post(cta, 1u);

    const float* wrow = WsT + j * REC_P;

    for (int t = 1; t < Tsz; ++t) {
        flag_wait((unsigned)t);

        for (int i = tid; i < 32 * 128; i += 256) {
            int rr = i >> 7;
            int c  = (i & 127) * 4;
            float4 v = *reinterpret_cast<const float4*>(
                buf + ((size_t)(b0 + rr) * Tsz + (t - 1)) * Hsz + c);
            *reinterpret_cast<float4*>(Ash + rr * Hsz + c) = v;
        }
        __syncthreads();

        unsigned long long a[4]  = {0ull, 0ull, 0ull, 0ull};
        unsigned long long aB[4] = {0ull, 0ull, 0ull, 0ull};

#pragma unroll 4
        for (int k = 0; k < Hsz; k += 8) {
            ulonglong2 w0 = *reinterpret_cast<const ulonglong2*>(wrow + k);
            ulonglong2 w1 = *reinterpret_cast<const ulonglong2*>(wrow + k + 4);
#pragma unroll
            for (int i = 0; i < 4; ++i) {
                const float* xr = Ash + (r0 + i) * Hsz + k;
                ulonglong2 x0 = *reinterpret_cast<const ulonglong2*>(xr);
                ulonglong2 x1 = *reinterpret_cast<const ulonglong2*>(xr + 4);
                a[i]  = ffma2(x0.x, w0.x, a[i]);
                aB[i] = ffma2(x0.y, w0.y, aB[i]);
                a[i]  = ffma2(x1.x, w1.x, a[i]);
                aB[i] = ffma2(x1.y, w1.y, aB[i]);
            }
        }

#pragma unroll
        for (int i = 0; i < 4; ++i) {
            float* o = buf + ((size_t)(b0 + r0 + i) * Tsz + t) * Hsz + n0 + j;
            *o = fmaxf(*o + f2sum(a[i]) + f2sum(aB[i]), 0.f);
        }
        if (t < Tsz - 1) flag_post(cta, (unsigned)(t + 1));
    }
}

// ---------------------------------------------------------------------------
// Final FC: out[b,c] = sum_i flat[b,i] * Wfc[c,i] + bfc[c]
// 64 CTAs; each handles 4 batch rows -> W_fc re-read from L2 only 64x.
// ---------------------------------------------------------------------------
__global__ void __launch_bounds__(256) fc_kernel(
    const float* __restrict__ flat, const float* __restrict__ Wfc,
    const float* __restrict__ bfc, float* __restrict__ out)
{
    const int b = blockIdx.x;   // 0..63
    const float* xr[4];
#pragma unroll
    for (int rr = 0; rr < 4; ++rr)
        xr[rr] = flat + (size_t)(b + rr * 64) * (Tsz * Hsz);

    float acc[4][Csz];
#pragma unroll
    for (int rr = 0; rr < 4; ++rr)
#pragma unroll
        for (int c = 0; c < Csz; ++c) acc[rr][c] = 0.f;

    for (int i = threadIdx.x * 4; i < Tsz * Hsz; i += 256 * 4) {
        float4 x[4];
#pragma unroll
        for (int rr = 0; rr < 4; ++rr)
            x[rr] = *reinterpret_cast<const float4*>(xr[rr] + i);
#pragma unroll
        for (int c = 0; c < Csz; ++c) {
            float4 w = *reinterpret_cast<const float4*>(
                Wfc + (size_t)c * (Tsz * Hsz) + i);
#pragma unroll
            for (int rr = 0; rr < 4; ++rr)
                acc[rr][c] += x[rr].x * w.x + x[rr].y * w.y
                            + x[rr].z * w.z + x[rr].w * w.w;
        }
    }

#pragma unroll
    for (int rr = 0; rr < 4; ++rr)
#pragma unroll
        for (int c = 0; c < Csz; ++c)
#pragma unroll
            for (int off = 16; off > 0; off >>= 1)
                acc[rr][c] += __shfl_down_sync(0xffffffffu, acc[rr][c], off);

    __shared__ float part[4][Csz][8];
    const int warp = threadIdx.x >> 5;
    const int lane = threadIdx.x & 31;
    if (lane == 0) {
#pragma unroll
        for (int rr = 0; rr < 4; ++rr)
#pragma unroll
            for (int c = 0; c < Csz; ++c) part[rr][c][warp] = acc[rr][c];
    }
    __syncthreads();
    if (threadIdx.x < 4 * Csz) {
        int rr = threadIdx.x / Csz;
        int c  = threadIdx.x % Csz;
        float s = 0.f;
#pragma unroll
        for (int w = 0; w < 8; ++w) s += part[rr][c][w];
        out[(b + rr * 64) * Csz + c] = s + bfc[c];
    }
}

// ---------------------------------------------------------------------------
// kernel_launch: proj0 -> reset,rec0_fused(+proj1) -> reset,rec1 -> fc
// ---------------------------------------------------------------------------
extern "C" void kernel_launch(void* const* d_in, const int* in_sizes, int n_in,
                              void* d_out, int out_size)
{
    (void)in_sizes; (void)n_in; (void)out_size;
    const float* x     = (const float*)d_in[0];
    const float* W_ih0 = (const float*)d_in[1];
    const float* W_hh0 = (const float*)d_in[2];
    const float* b_ih0 = (const float*)d_in[3];
    const float* b_hh0 = (const float*)d_in[4];
    const float* W_ih1 = (const float*)d_in[5];
    const float* W_hh1 = (const float*)d_in[6];
    const float* b_ih1 = (const float*)d_in[7];
    const float* b_hh1 = (const float*)d_in[8];
    const float* W_fc  = (const float*)d_in[9];
    const float* b_fc  = (const float*)d_in[10];
    float* out = (float*)d_out;

    float* buf0 = nullptr;
    float* buf1 = nullptr;
    cudaGetSymbolAddress((void**)&buf0, g_buf0);
    cudaGetSymbolAddress((void**)&buf1, g_buf1);

    cudaFuncSetAttribute(rnn_rec0_fused,
                         cudaFuncAttributeMaxDynamicSharedMemorySize,
                         REC0_SMEM_BYTES);
    cudaFuncSetAttribute(rnn_rec,
                         cudaFuncAttributeMaxDynamicSharedMemorySize,
                         REC_SMEM_BYTES);

    dim3 pgrid(Hsz / PJ_BN, (Bsz * Tsz) / PJ_BM);   // (8, 256)

    // Layer 0 projection
    proj_gemm<<<pgrid, 256>>>(x, W_ih0, b_ih0, b_hh0, buf0, Fsz);
    // Layer 0 recurrence fused with layer 1 projection
    reset_flags<<<1, 128>>>();
    rnn_rec0_fused<<<REC_NBLK, 256, REC0_SMEM_BYTES>>>(
        buf0, buf1, W_hh0, W_ih1, b_ih1, b_hh1);
    // Layer 1 recurrence
    reset_flags<<<1, 128>>>();
    rnn_rec<<<REC_NBLK, 256, REC_SMEM_BYTES>>>(buf1, W_hh1);
    // Classifier
    fc_kernel<<<64, 256>>>(buf1, W_fc, b_fc, out);
}

// round 12
// speedup vs baseline: 1.4374x; 1.3758x over previous
#include <cuda_runtime.h>
#include <cstdint>

#define Bsz 256
#define Tsz 128
#define Fsz 256
#define Hsz 512
#define Csz 10

// Scratch: proj/h buffers, written in place by the recurrence.
__device__ float g_buf0[Bsz * Tsz * Hsz];   // 64 MB
__device__ float g_buf1[Bsz * Tsz * Hsz];   // 64 MB

// Distributed barrier: one padded flag per CTA (128B apart).
#define REC_NBLK 128
__device__ unsigned g_flag[REC_NBLK * 32];

__global__ void reset_flags()
{
    if (threadIdx.x < REC_NBLK) g_flag[threadIdx.x * 32] = 0u;
}

// ---------------------------------------------------------------------------
// f32x2 packed FMA helpers (Blackwell FFMA2) — used by the projection GEMM.
// ---------------------------------------------------------------------------
__device__ __forceinline__ unsigned long long ffma2(
    unsigned long long a, unsigned long long b, unsigned long long c)
{
    unsigned long long d;
    asm("fma.rn.f32x2 %0, %1, %2, %3;" : "=l"(d) : "l"(a), "l"(b), "l"(c));
    return d;
}
__device__ __forceinline__ float f2sum(unsigned long long v)
{
    float lo, hi;
    asm("mov.b64 {%0, %1}, %2;" : "=f"(lo), "=f"(hi) : "l"(v));
    return lo + hi;
}

// ---------------------------------------------------------------------------
// TF32 helpers for the tensor-core recurrence.
// ---------------------------------------------------------------------------
__device__ __forceinline__ uint32_t f2tf32(float x)
{
    uint32_t r;
    asm("cvt.rna.tf32.f32 %0, %1;" : "=r"(r) : "f"(x));
    return r;
}

__device__ __forceinline__ void mma_tf32(
    float& d0, float& d1, float& d2, float& d3,
    uint32_t a0, uint32_t a1, uint32_t a2, uint32_t a3,
    uint32_t b0, uint32_t b1)
{
    asm volatile(
        "mma.sync.aligned.m16n8k8.row.col.f32.tf32.tf32.f32 "
        "{%0,%1,%2,%3}, {%4,%5,%6,%7}, {%8,%9}, {%0,%1,%2,%3};\n"
        : "+f"(d0), "+f"(d1), "+f"(d2), "+f"(d3)
        : "r"(a0), "r"(a1), "r"(a2), "r"(a3), "r"(b0), "r"(b1));
}

// ---------------------------------------------------------------------------
// Projection GEMM: out[m,n] = sum_k A[m,k]*Wt[n,k] + bias1[n] + bias2[n]
// Used for layer-0 (K=256) and layer-1 (K=512) input projections.
// ---------------------------------------------------------------------------
#define PJ_BM 128
#define PJ_BN 64
#define PJ_BK 16
#define PJ_PA 20
#define PJ_PB 20

__global__ void __launch_bounds__(256, 2) proj_gemm(
    const float* __restrict__ A, const float* __restrict__ Wt,
    const float* __restrict__ bias1, const float* __restrict__ bias2,
    float* __restrict__ out, int K)
{
    __shared__ float As[PJ_BM * PJ_PA];
    __shared__ float Bs[PJ_BN * PJ_PB];

    const int tid = threadIdx.x;
    const int m0 = blockIdx.y * PJ_BM;
    const int n0 = blockIdx.x * PJ_BN;
    const int tx = tid & 15;
    const int ty = tid >> 4;

    const int arow = tid >> 2;
    const int ach  = tid & 3;
    const float* apg = A + (size_t)(m0 + arow) * K + ach * 4;
    const int bcol = tid >> 2;
    const float* bpg = Wt + (size_t)(n0 + bcol) * K + ach * 4;

    unsigned long long acc[8][4];
#pragma unroll
    for (int i = 0; i < 8; ++i)
#pragma unroll
        for (int c = 0; c < 4; ++c) acc[i][c] = 0ull;

    float4 ra0 = *reinterpret_cast<const float4*>(apg);
    float4 ra1 = *reinterpret_cast<const float4*>(apg + (size_t)64 * K);
    float4 rb  = *reinterpret_cast<const float4*>(bpg);

    const int S = K / PJ_BK;
    for (int s = 0; s < S; ++s) {
        *reinterpret_cast<float4*>(&As[arow * PJ_PA + ach * 4])        = ra0;
        *reinterpret_cast<float4*>(&As[(arow + 64) * PJ_PA + ach * 4]) = ra1;
        *reinterpret_cast<float4*>(&Bs[bcol * PJ_PB + ach * 4])        = rb;
        __syncthreads();

        if (s + 1 < S) {
            const size_t off = (size_t)(s + 1) * PJ_BK;
            ra0 = *reinterpret_cast<const float4*>(apg + off);
            ra1 = *reinterpret_cast<const float4*>(apg + (size_t)64 * K + off);
            rb  = *reinterpret_cast<const float4*>(bpg + off);
        }

#pragma unroll
        for (int kk = 0; kk < PJ_BK; kk += 4) {
            ulonglong2 bv[4];
#pragma unroll
            for (int c = 0; c < 4; ++c)
                bv[c] = *reinterpret_cast<const ulonglong2*>(
                    &Bs[(tx + c * 16) * PJ_PB + kk]);
#pragma unroll
            for (int i = 0; i < 8; ++i) {
                ulonglong2 av = *reinterpret_cast<const ulonglong2*>(
                    &As[(ty * 8 + i) * PJ_PA + kk]);
#pragma unroll
                for (int c = 0; c < 4; ++c) {
                    acc[i][c] = ffma2(av.x, bv[c].x, acc[i][c]);
                    acc[i][c] = ffma2(av.y, bv[c].y, acc[i][c]);
                }
            }
        }
        __syncthreads();
    }

    float bb[4];
#pragma unroll
    for (int c = 0; c < 4; ++c)
        bb[c] = bias1[n0 + tx + c * 16] + bias2[n0 + tx + c * 16];

#pragma unroll
    for (int i = 0; i < 8; ++i) {
        float* orow = out + (size_t)(m0 + ty * 8 + i) * Hsz + n0 + tx;
#pragma unroll
        for (int c = 0; c < 4; ++c)
            orow[c * 16] = f2sum(acc[i][c]) + bb[c];
    }
}

// ---------------------------------------------------------------------------
// Distributed-flag barrier primitives.
// ---------------------------------------------------------------------------
__device__ __forceinline__ void flag_post(int cta, unsigned val)
{
    __syncthreads();
    if (threadIdx.x == 0) {
        __threadfence();             // release
        *(volatile unsigned*)&g_flag[cta * 32] = val;
    }
}

__device__ __forceinline__ void flag_wait(unsigned val)
{
    if (threadIdx.x < REC_NBLK) {
        while (*(volatile unsigned*)&g_flag[threadIdx.x * 32] < val) { }
        __threadfence();             // acquire
    }
    __syncthreads();
}

// ---------------------------------------------------------------------------
// Tensor-core recurrence (both layers).
// 128 CTAs x 256 threads (8 warps), persistent over t with flag barrier.
// CTA tile: 32 batch rows x 32 hidden cols. Warp w owns k in [64w, 64w+64);
// each warp computes the full 32x32 tile for its k-slice -> smem reduction.
//
// 3xTF32 for fp32 accuracy: h = Xhi + Xlo (tf32 split), W = Whi + Wlo:
//   acc += Xhi*Whi + Xlo*Whi + Xhi*Wlo    (error ~2^-22)
// Whi/Wlo B-fragments live in REGISTERS for all 128 steps (128 regs/thread).
// Xhi/Xlo staged per step into smem with pitch 516 -> A-frag LDS.32 loads
// hit banks (4g + tg): all 32 lanes distinct, conflict-free.
// ---------------------------------------------------------------------------
#define REC_AP 516                              // smem pitch (4 mod 32)
#define REC_SMEM_FLOATS (2 * 32 * REC_AP)       // Ahi + Alo
#define REC_SMEM_BYTES (REC_SMEM_FLOATS * 4)    // 132096 B
#define RED_PITCH 34                            // reduction row pitch
#define RED_WSTRIDE (32 * RED_PITCH)            // 1088 floats per warp block

__global__ void __launch_bounds__(256) rnn_rec_mma(
    float* __restrict__ buf, const float* __restrict__ Whh)
{
    extern __shared__ float sm[];
    float* Ahi = sm;                  // [32][REC_AP]
    float* Alo = sm + 32 * REC_AP;    // [32][REC_AP]
    float* red = sm;                  // reused after compute (8*1088 floats)

    const int tid  = threadIdx.x;
    const int cta  = blockIdx.x;
    const int wid  = tid >> 5;        // warp 0..7 -> k-slice
    const int lane = tid & 31;
    const int g    = lane >> 2;       // groupID 0..7
    const int tg   = lane & 3;        // thread-in-group 0..3

    const int tile_m = cta >> 4;      // 0..7  batch rows
    const int tile_n = cta & 15;      // 0..15 hidden cols
    const int b0 = tile_m * 32;
    const int n0 = tile_n * 32;

    // --- Load W fragments (hi/lo tf32 split) into registers, once. ---
    // B frag (col-major 8k x 8n): b0 = W[n0+nf*8+g][kbase+tg],
    //                             b1 = W[n0+nf*8+g][kbase+tg+4]
    uint32_t Bhi[4][8][2], Blo[4][8][2];
#pragma unroll
    for (int nf = 0; nf < 4; ++nf) {
#pragma unroll
        for (int kf = 0; kf < 8; ++kf) {
            const float* wp = Whh + (size_t)(n0 + nf * 8 + g) * Hsz
                            + wid * 64 + kf * 8 + tg;
            float w0 = wp[0];
            float w1 = wp[4];
            uint32_t h0 = f2tf32(w0);
            uint32_t h1 = f2tf32(w1);
            Bhi[nf][kf][0] = h0;
            Bhi[nf][kf][1] = h1;
            Blo[nf][kf][0] = f2tf32(w0 - __uint_as_float(h0));
            Blo[nf][kf][1] = f2tf32(w1 - __uint_as_float(h1));
        }
    }

    // t = 0: h_0 = relu(proj_0)
    for (int i = tid; i < 32 * 32; i += 256) {
        int rr = i >> 5;
        int c  = i & 31;
        float* p = buf + ((size_t)(b0 + rr) * Tsz + 0) * Hsz + n0 + c;
        *p = fmaxf(*p, 0.f);
    }
    flag_post(cta, 1u);

    // Per-thread constant part of A-frag smem offsets.
    const int abase = g * REC_AP + wid * 64 + tg;

    for (int t = 1; t < Tsz; ++t) {
        flag_wait((unsigned)t);   // all CTAs finished step t-1; guards smem reuse

        // Stage h_{t-1} rows into smem as tf32 hi/lo split.
        for (int i = tid; i < 32 * 128; i += 256) {
            int rr = i >> 7;
            int c  = (i & 127) * 4;
            float4 v = *reinterpret_cast<const float4*>(
                buf + ((size_t)(b0 + rr) * Tsz + (t - 1)) * Hsz + c);
            uint32_t hx = f2tf32(v.x), hy = f2tf32(v.y),
                     hz = f2tf32(v.z), hw = f2tf32(v.w);
            float4 hi4 = make_float4(__uint_as_float(hx), __uint_as_float(hy),
                                     __uint_as_float(hz), __uint_as_float(hw));
            float4 lo4 = make_float4(v.x - hi4.x, v.y - hi4.y,
                                     v.z - hi4.z, v.w - hi4.w);
            *reinterpret_cast<float4*>(Ahi + rr * REC_AP + c) = hi4;
            *reinterpret_cast<float4*>(Alo + rr * REC_AP + c) = lo4;
        }
        __syncthreads();

        float acc[2][4][4];
#pragma unroll
        for (int mf = 0; mf < 2; ++mf)
#pragma unroll
            for (int nf = 0; nf < 4; ++nf)
#pragma unroll
                for (int i = 0; i < 4; ++i) acc[mf][nf][i] = 0.f;

        const uint32_t* AhiU = reinterpret_cast<const uint32_t*>(Ahi);
        const uint32_t* AloU = reinterpret_cast<const uint32_t*>(Alo);

#pragma unroll
        for (int kf = 0; kf < 8; ++kf) {
#pragma unroll
            for (int mf = 0; mf < 2; ++mf) {
                const int off = abase + kf * 8 + mf * (16 * REC_AP);
                uint32_t ah0 = AhiU[off];
                uint32_t ah1 = AhiU[off + 8 * REC_AP];
                uint32_t ah2 = AhiU[off + 4];
                uint32_t ah3 = AhiU[off + 8 * REC_AP + 4];
                uint32_t al0 = AloU[off];
                uint32_t al1 = AloU[off + 8 * REC_AP];
                uint32_t al2 = AloU[off + 4];
                uint32_t al3 = AloU[off + 8 * REC_AP + 4];
#pragma unroll
                for (int nf = 0; nf < 4; ++nf) {
                    mma_tf32(acc[mf][nf][0], acc[mf][nf][1],
                             acc[mf][nf][2], acc[mf][nf][3],
                             ah0, ah1, ah2, ah3,
                             Bhi[nf][kf][0], Bhi[nf][kf][1]);
                    mma_tf32(acc[mf][nf][0], acc[mf][nf][1],
                             acc[mf][nf][2], acc[mf][nf][3],
                             al0, al1, al2, al3,
                             Bhi[nf][kf][0], Bhi[nf][kf][1]);
                    mma_tf32(acc[mf][nf][0], acc[mf][nf][1],
                             acc[mf][nf][2], acc[mf][nf][3],
                             ah0, ah1, ah2, ah3,
                             Blo[nf][kf][0], Blo[nf][kf][1]);
                }
            }
        }
        __syncthreads();   // done reading Ahi/Alo -> safe to reuse as red

        // Store per-warp partials: D frag element (m,n):
        //   c0:(g, 2tg) c1:(g, 2tg+1) c2:(g+8, 2tg) c3:(g+8, 2tg+1)
        {
            float* rw = red + wid * RED_WSTRIDE;
#pragma unroll
            for (int mf = 0; mf < 2; ++mf) {
#pragma unroll
                for (int nf = 0; nf < 4; ++nf) {
                    int m = mf * 16 + g;
                    int n = nf * 8 + 2 * tg;
                    *reinterpret_cast<float2*>(&rw[m * RED_PITCH + n]) =
                        make_float2(acc[mf][nf][0], acc[mf][nf][1]);
                    *reinterpret_cast<float2*>(&rw[(m + 8) * RED_PITCH + n]) =
                        make_float2(acc[mf][nf][2], acc[mf][nf][3]);
                }
            }
        }
        __syncthreads();

        // Reduce 8 warps' partials; h_t = relu(proj_t + sum), in place.
        {
            int m  = tid >> 3;          // 0..31
            int nc = (tid & 7) * 4;     // 0..28
            float2 s0 = make_float2(0.f, 0.f);
            float2 s1 = make_float2(0.f, 0.f);
#pragma unroll
            for (int w = 0; w < 8; ++w) {
                const float* rw = red + w * RED_WSTRIDE + m * RED_PITCH + nc;
                float2 v0 = *reinterpret_cast<const float2*>(rw);
                float2 v1 = *reinterpret_cast<const float2*>(rw + 2);
                s0.x += v0.x; s0.y += v0.y;
                s1.x += v1.x; s1.y += v1.y;
            }
            float* p = buf + ((size_t)(b0 + m) * Tsz + t) * Hsz + n0 + nc;
            float4 q = *reinterpret_cast<float4*>(p);
            q.x = fmaxf(q.x + s0.x, 0.f);
            q.y = fmaxf(q.y + s0.y, 0.f);
            q.z = fmaxf(q.z + s1.x, 0.f);
            q.w = fmaxf(q.w + s1.y, 0.f);
            *reinterpret_cast<float4*>(p) = q;
        }

        if (t < Tsz - 1) flag_post(cta, (unsigned)(t + 1));
    }
}

// ---------------------------------------------------------------------------
// Final FC: out[b,c] = sum_i flat[b,i] * Wfc[c,i] + bfc[c]
// 64 CTAs; each handles 4 batch rows.
// ---------------------------------------------------------------------------
__global__ void __launch_bounds__(256) fc_kernel(
    const float* __restrict__ flat, const float* __restrict__ Wfc,
    const float* __restrict__ bfc, float* __restrict__ out)
{
    const int b = blockIdx.x;   // 0..63
    const float* xr[4];
#pragma unroll
    for (int rr = 0; rr < 4; ++rr)
        xr[rr] = flat + (size_t)(b + rr * 64) * (Tsz * Hsz);

    float acc[4][Csz];
#pragma unroll
    for (int rr = 0; rr < 4; ++rr)
#pragma unroll
        for (int c = 0; c < Csz; ++c) acc[rr][c] = 0.f;

    for (int i = threadIdx.x * 4; i < Tsz * Hsz; i += 256 * 4) {
        float4 x[4];
#pragma unroll
        for (int rr = 0; rr < 4; ++rr)
            x[rr] = *reinterpret_cast<const float4*>(xr[rr] + i);
#pragma unroll
        for (int c = 0; c < Csz; ++c) {
            float4 w = *reinterpret_cast<const float4*>(
                Wfc + (size_t)c * (Tsz * Hsz) + i);
#pragma unroll
            for (int rr = 0; rr < 4; ++rr)
                acc[rr][c] += x[rr].x * w.x + x[rr].y * w.y
                            + x[rr].z * w.z + x[rr].w * w.w;
        }
    }

#pragma unroll
    for (int rr = 0; rr < 4; ++rr)
#pragma unroll
        for (int c = 0; c < Csz; ++c)
#pragma unroll
            for (int off = 16; off > 0; off >>= 1)
                acc[rr][c] += __shfl_down_sync(0xffffffffu, acc[rr][c], off);

    __shared__ float part[4][Csz][8];
    const int warp = threadIdx.x >> 5;
    const int lane = threadIdx.x & 31;
    if (lane == 0) {
#pragma unroll
        for (int rr = 0; rr < 4; ++rr)
#pragma unroll
            for (int c = 0; c < Csz; ++c) part[rr][c][warp] = acc[rr][c];
    }
    __syncthreads();
    if (threadIdx.x < 4 * Csz) {
        int rr = threadIdx.x / Csz;
        int c  = threadIdx.x % Csz;
        float s = 0.f;
#pragma unroll
        for (int w = 0; w < 8; ++w) s += part[rr][c][w];
        out[(b + rr * 64) * Csz + c] = s + bfc[c];
    }
}

// ---------------------------------------------------------------------------
// kernel_launch: proj0 -> reset,rec0(mma) -> proj1 -> reset,rec1(mma) -> fc
// ---------------------------------------------------------------------------
extern "C" void kernel_launch(void* const* d_in, const int* in_sizes, int n_in,
                              void* d_out, int out_size)
{
    (void)in_sizes; (void)n_in; (void)out_size;
    const float* x     = (const float*)d_in[0];
    const float* W_ih0 = (const float*)d_in[1];
    const float* W_hh0 = (const float*)d_in[2];
    const float* b_ih0 = (const float*)d_in[3];
    const float* b_hh0 = (const float*)d_in[4];
    const float* W_ih1 = (const float*)d_in[5];
    const float* W_hh1 = (const float*)d_in[6];
    const float* b_ih1 = (const float*)d_in[7];
    const float* b_hh1 = (const float*)d_in[8];
    const float* W_fc  = (const float*)d_in[9];
    const float* b_fc  = (const float*)d_in[10];
    float* out = (float*)d_out;

    float* buf0 = nullptr;
    float* buf1 = nullptr;
    cudaGetSymbolAddress((void**)&buf0, g_buf0);
    cudaGetSymbolAddress((void**)&buf1, g_buf1);

    cudaFuncSetAttribute(rnn_rec_mma,
                         cudaFuncAttributeMaxDynamicSharedMemorySize,
                         REC_SMEM_BYTES);

    dim3 pgrid(Hsz / PJ_BN, (Bsz * Tsz) / PJ_BM);   // (8, 256)

    // Layer 0
    proj_gemm<<<pgrid, 256>>>(x, W_ih0, b_ih0, b_hh0, buf0, Fsz);
    reset_flags<<<1, 128>>>();
    rnn_rec_mma<<<REC_NBLK, 256, REC_SMEM_BYTES>>>(buf0, W_hh0);

    // Layer 1
    proj_gemm<<<pgrid, 256>>>(buf0, W_ih1, b_ih1, b_hh1, buf1, Hsz);
    reset_flags<<<1, 128>>>();
    rnn_rec_mma<<<REC_NBLK, 256, REC_SMEM_BYTES>>>(buf1, W_hh1);

    // Classifier
    fc_kernel<<<64, 256>>>(buf1, W_fc, b_fc, out);
}

// round 13
// speedup vs baseline: 1.5310x; 1.0652x over previous
#include <cuda_runtime.h>
#include <cstdint>

#define Bsz 256
#define Tsz 128
#define Fsz 256
#define Hsz 512
#define Csz 10

// Scratch: proj/h buffers, written in place by the recurrence.
__device__ float g_buf0[Bsz * Tsz * Hsz];   // 64 MB
__device__ float g_buf1[Bsz * Tsz * Hsz];   // 64 MB

// Distributed barrier: one padded flag per CTA (128B apart).
#define REC_NBLK 128
__device__ unsigned g_flag[REC_NBLK * 32];

__global__ void reset_flags()
{
    if (threadIdx.x < REC_NBLK) g_flag[threadIdx.x * 32] = 0u;
}

// ---------------------------------------------------------------------------
// TF32 helpers (shared by recurrence and projection).
// ---------------------------------------------------------------------------
__device__ __forceinline__ uint32_t f2tf32(float x)
{
    uint32_t r;
    asm("cvt.rna.tf32.f32 %0, %1;" : "=r"(r) : "f"(x));
    return r;
}

__device__ __forceinline__ void mma_tf32(
    float& d0, float& d1, float& d2, float& d3,
    uint32_t a0, uint32_t a1, uint32_t a2, uint32_t a3,
    uint32_t b0, uint32_t b1)
{
    asm volatile(
        "mma.sync.aligned.m16n8k8.row.col.f32.tf32.tf32.f32 "
        "{%0,%1,%2,%3}, {%4,%5,%6,%7}, {%8,%9}, {%0,%1,%2,%3};\n"
        : "+f"(d0), "+f"(d1), "+f"(d2), "+f"(d3)
        : "r"(a0), "r"(a1), "r"(a2), "r"(a3), "r"(b0), "r"(b1));
}

// ---------------------------------------------------------------------------
// Tensor-core projection GEMM: out[m,n] = sum_k A[m,k]*Wt[n,k] + b1[n]+b2[n]
// M = 32768, N = 512, K in {256, 512}. 3xTF32 split (error ~2^-22).
// BM=128, BN=64, BK=32. 8 warps in 4m x 2n grid; warp tile 32x32.
// Smem pitch 36: bank = (4*row + k) mod 32 -> conflict-free staging STS.128
// and fragment LDS.32 (same proof as the recurrence kernel).
// ---------------------------------------------------------------------------
#define PAP 36
#define PJS_ALO (128 * PAP)
#define PJS_BHI (2 * 128 * PAP)
#define PJS_BLO (2 * 128 * PAP + 64 * PAP)
#define PJ_SMEM_FLOATS (2 * 128 * PAP + 2 * 64 * PAP)
#define PJ_SMEM_BYTES (PJ_SMEM_FLOATS * 4)   // 55296 B

__global__ void __launch_bounds__(256, 2) proj_mma(
    const float* __restrict__ A, const float* __restrict__ Wt,
    const float* __restrict__ bias1, const float* __restrict__ bias2,
    float* __restrict__ out, int K)
{
    extern __shared__ float psm[];
    float* Ahi = psm;
    float* Alo = psm + PJS_ALO;
    float* Bhi = psm + PJS_BHI;
    float* Blo = psm + PJS_BLO;

    const int tid  = threadIdx.x;
    const int w    = tid >> 5;
    const int lane = tid & 31;
    const int wm   = w & 3;          // warp m-tile 0..3
    const int wn   = w >> 2;         // warp n-tile 0..1
    const int g    = lane >> 2;      // 0..7
    const int tg   = lane & 3;       // 0..3

    const int m0 = blockIdx.y * 128;
    const int n0 = blockIdx.x * 64;

    // Staging assignments (BK=32 floats per row per chunk).
    const int arow  = tid >> 1;           // 0..127
    const int apart = (tid & 1) * 16;     // two threads per A row
    const float* apg = A + (size_t)(m0 + arow) * K + apart;
    const int brow  = tid >> 2;           // 0..63
    const int bpart = (tid & 3) * 8;      // four threads per B row
    const float* bpg = Wt + (size_t)(n0 + brow) * K + bpart;

    float4 ra[4], rb[2];
#pragma unroll
    for (int u = 0; u < 4; ++u)
        ra[u] = *reinterpret_cast<const float4*>(apg + u * 4);
#pragma unroll
    for (int u = 0; u < 2; ++u)
        rb[u] = *reinterpret_cast<const float4*>(bpg + u * 4);

    float acc[2][4][4];
#pragma unroll
    for (int mf = 0; mf < 2; ++mf)
#pragma unroll
        for (int nf = 0; nf < 4; ++nf)
#pragma unroll
            for (int i = 0; i < 4; ++i) acc[mf][nf][i] = 0.f;

    const uint32_t* AhiU = reinterpret_cast<const uint32_t*>(Ahi);
    const uint32_t* AloU = reinterpret_cast<const uint32_t*>(Alo);
    const uint32_t* BhiU = reinterpret_cast<const uint32_t*>(Bhi);
    const uint32_t* BloU = reinterpret_cast<const uint32_t*>(Blo);

    const int S = K >> 5;
    for (int s = 0; s < S; ++s) {
        // Stage current chunk: tf32 hi/lo split -> smem planes.
#pragma unroll
        for (int u = 0; u < 4; ++u) {
            float4 v = ra[u];
            float4 hi = make_float4(
                __uint_as_float(f2tf32(v.x)), __uint_as_float(f2tf32(v.y)),
                __uint_as_float(f2tf32(v.z)), __uint_as_float(f2tf32(v.w)));
            float4 lo = make_float4(v.x - hi.x, v.y - hi.y,
                                    v.z - hi.z, v.w - hi.w);
            const int o = arow * PAP + apart + u * 4;
            *reinterpret_cast<float4*>(&Ahi[o]) = hi;
            *reinterpret_cast<float4*>(&Alo[o]) = lo;
        }
#pragma unroll
        for (int u = 0; u < 2; ++u) {
            float4 v = rb[u];
            float4 hi = make_float4(
                __uint_as_float(f2tf32(v.x)), __uint_as_float(f2tf32(v.y)),
                __uint_as_float(f2tf32(v.z)), __uint_as_float(f2tf32(v.w)));
            float4 lo = make_float4(v.x - hi.x, v.y - hi.y,
                                    v.z - hi.z, v.w - hi.w);
            const int o = brow * PAP + bpart + u * 4;
            *reinterpret_cast<float4*>(&Bhi[o]) = hi;
            *reinterpret_cast<float4*>(&Blo[o]) = lo;
        }
        __syncthreads();

        // Prefetch next chunk while computing this one.
        if (s + 1 < S) {
            const size_t off = (size_t)(s + 1) * 32;
#pragma unroll
            for (int u = 0; u < 4; ++u)
                ra[u] = *reinterpret_cast<const float4*>(apg + off + u * 4);
#pragma unroll
            for (int u = 0; u < 2; ++u)
                rb[u] = *reinterpret_cast<const float4*>(bpg + off + u * 4);
        }

#pragma unroll
        for (int kf = 0; kf < 4; ++kf) {
            uint32_t ah[2][4], al[2][4];
#pragma unroll
            for (int mf = 0; mf < 2; ++mf) {
                const int o = (wm * 32 + mf * 16 + g) * PAP + kf * 8 + tg;
                ah[mf][0] = AhiU[o];
                ah[mf][1] = AhiU[o + 8 * PAP];
                ah[mf][2] = AhiU[o + 4];
                ah[mf][3] = AhiU[o + 8 * PAP + 4];
                al[mf][0] = AloU[o];
                al[mf][1] = AloU[o + 8 * PAP];
                al[mf][2] = AloU[o + 4];
                al[mf][3] = AloU[o + 8 * PAP + 4];
            }
            uint32_t bh[4][2], bl[4][2];
#pragma unroll
            for (int nf = 0; nf < 4; ++nf) {
                const int o = (wn * 32 + nf * 8 + g) * PAP + kf * 8 + tg;
                bh[nf][0] = BhiU[o];
                bh[nf][1] = BhiU[o + 4];
                bl[nf][0] = BloU[o];
                bl[nf][1] = BloU[o + 4];
            }
#pragma unroll
            for (int mf = 0; mf < 2; ++mf) {
#pragma unroll
                for (int nf = 0; nf < 4; ++nf) {
                    mma_tf32(acc[mf][nf][0], acc[mf][nf][1],
                             acc[mf][nf][2], acc[mf][nf][3],
                             ah[mf][0], ah[mf][1], ah[mf][2], ah[mf][3],
                             bh[nf][0], bh[nf][1]);
                    mma_tf32(acc[mf][nf][0], acc[mf][nf][1],
                             acc[mf][nf][2], acc[mf][nf][3],
                             al[mf][0], al[mf][1], al[mf][2], al[mf][3],
                             bh[nf][0], bh[nf][1]);
                    mma_tf32(acc[mf][nf][0], acc[mf][nf][1],
                             acc[mf][nf][2], acc[mf][nf][3],
                             ah[mf][0], ah[mf][1], ah[mf][2], ah[mf][3],
                             bl[nf][0], bl[nf][1]);
                }
            }
        }
        __syncthreads();
    }

    // Epilogue: add biases, write fp32. D frag (m,n): c0:(g,2tg) c1:(g,2tg+1)
    // c2:(g+8,2tg) c3:(g+8,2tg+1).
#pragma unroll
    for (int nf = 0; nf < 4; ++nf) {
        const int n = n0 + wn * 32 + nf * 8 + 2 * tg;
        const float b0 = bias1[n] + bias2[n];
        const float b1 = bias1[n + 1] + bias2[n + 1];
#pragma unroll
        for (int mf = 0; mf < 2; ++mf) {
            const int m = m0 + wm * 32 + mf * 16 + g;
            *reinterpret_cast<float2*>(&out[(size_t)m * Hsz + n]) =
                make_float2(acc[mf][nf][0] + b0, acc[mf][nf][1] + b1);
            *reinterpret_cast<float2*>(&out[(size_t)(m + 8) * Hsz + n]) =
                make_float2(acc[mf][nf][2] + b0, acc[mf][nf][3] + b1);
        }
    }
}

// ---------------------------------------------------------------------------
// Distributed-flag barrier primitives.
// ---------------------------------------------------------------------------
__device__ __forceinline__ void flag_post(int cta, unsigned val)
{
    __syncthreads();
    if (threadIdx.x == 0) {
        __threadfence();             // release
        *(volatile unsigned*)&g_flag[cta * 32] = val;
    }
}

__device__ __forceinline__ void flag_wait(unsigned val)
{
    if (threadIdx.x < REC_NBLK) {
        while (*(volatile unsigned*)&g_flag[threadIdx.x * 32] < val) { }
        __threadfence();             // acquire
    }
    __syncthreads();
}

// ---------------------------------------------------------------------------
// Tensor-core recurrence (both layers) — unchanged from R12 (passing).
// ---------------------------------------------------------------------------
#define REC_AP 516
#define REC_SMEM_FLOATS (2 * 32 * REC_AP)
#define REC_SMEM_BYTES (REC_SMEM_FLOATS * 4)    // 132096 B
#define RED_PITCH 34
#define RED_WSTRIDE (32 * RED_PITCH)

__global__ void __launch_bounds__(256) rnn_rec_mma(
    float* __restrict__ buf, const float* __restrict__ Whh)
{
    extern __shared__ float sm[];
    float* Ahi = sm;                  // [32][REC_AP]
    float* Alo = sm + 32 * REC_AP;    // [32][REC_AP]
    float* red = sm;                  // reused after compute

    const int tid  = threadIdx.x;
    const int cta  = blockIdx.x;
    const int wid  = tid >> 5;
    const int lane = tid & 31;
    const int g    = lane >> 2;
    const int tg   = lane & 3;

    const int tile_m = cta >> 4;
    const int tile_n = cta & 15;
    const int b0 = tile_m * 32;
    const int n0 = tile_n * 32;

    uint32_t Bhi[4][8][2], Blo[4][8][2];
#pragma unroll
    for (int nf = 0; nf < 4; ++nf) {
#pragma unroll
        for (int kf = 0; kf < 8; ++kf) {
            const float* wp = Whh + (size_t)(n0 + nf * 8 + g) * Hsz
                            + wid * 64 + kf * 8 + tg;
            float w0 = wp[0];
            float w1 = wp[4];
            uint32_t h0 = f2tf32(w0);
            uint32_t h1 = f2tf32(w1);
            Bhi[nf][kf][0] = h0;
            Bhi[nf][kf][1] = h1;
            Blo[nf][kf][0] = f2tf32(w0 - __uint_as_float(h0));
            Blo[nf][kf][1] = f2tf32(w1 - __uint_as_float(h1));
        }
    }

    for (int i = tid; i < 32 * 32; i += 256) {
        int rr = i >> 5;
        int c  = i & 31;
        float* p = buf + ((size_t)(b0 + rr) * Tsz + 0) * Hsz + n0 + c;
        *p = fmaxf(*p, 0.f);
    }
    flag_post(cta, 1u);

    const int abase = g * REC_AP + wid * 64 + tg;

    for (int t = 1; t < Tsz; ++t) {
        flag_wait((unsigned)t);

        for (int i = tid; i < 32 * 128; i += 256) {
            int rr = i >> 7;
            int c  = (i & 127) * 4;
            float4 v = *reinterpret_cast<const float4*>(
                buf + ((size_t)(b0 + rr) * Tsz + (t - 1)) * Hsz + c);
            uint32_t hx = f2tf32(v.x), hy = f2tf32(v.y),
                     hz = f2tf32(v.z), hw = f2tf32(v.w);
            float4 hi4 = make_float4(__uint_as_float(hx), __uint_as_float(hy),
                                     __uint_as_float(hz), __uint_as_float(hw));
            float4 lo4 = make_float4(v.x - hi4.x, v.y - hi4.y,
                                     v.z - hi4.z, v.w - hi4.w);
            *reinterpret_cast<float4*>(Ahi + rr * REC_AP + c) = hi4;
            *reinterpret_cast<float4*>(Alo + rr * REC_AP + c) = lo4;
        }
        __syncthreads();

        float acc[2][4][4];
#pragma unroll
        for (int mf = 0; mf < 2; ++mf)
#pragma unroll
            for (int nf = 0; nf < 4; ++nf)
#pragma unroll
                for (int i = 0; i < 4; ++i) acc[mf][nf][i] = 0.f;

        const uint32_t* AhiU = reinterpret_cast<const uint32_t*>(Ahi);
        const uint32_t* AloU = reinterpret_cast<const uint32_t*>(Alo);

#pragma unroll
        for (int kf = 0; kf < 8; ++kf) {
#pragma unroll
            for (int mf = 0; mf < 2; ++mf) {
                const int off = abase + kf * 8 + mf * (16 * REC_AP);
                uint32_t ah0 = AhiU[off];
                uint32_t ah1 = AhiU[off + 8 * REC_AP];
                uint32_t ah2 = AhiU[off + 4];
                uint32_t ah3 = AhiU[off + 8 * REC_AP + 4];
                uint32_t al0 = AloU[off];
                uint32_t al1 = AloU[off + 8 * REC_AP];
                uint32_t al2 = AloU[off + 4];
                uint32_t al3 = AloU[off + 8 * REC_AP + 4];
#pragma unroll
                for (int nf = 0; nf < 4; ++nf) {
                    mma_tf32(acc[mf][nf][0], acc[mf][nf][1],
                             acc[mf][nf][2], acc[mf][nf][3],
                             ah0, ah1, ah2, ah3,
                             Bhi[nf][kf][0], Bhi[nf][kf][1]);
                    mma_tf32(acc[mf][nf][0], acc[mf][nf][1],
                             acc[mf][nf][2], acc[mf][nf][3],
                             al0, al1, al2, al3,
                             Bhi[nf][kf][0], Bhi[nf][kf][1]);
                    mma_tf32(acc[mf][nf][0], acc[mf][nf][1],
                             acc[mf][nf][2], acc[mf][nf][3],
                             ah0, ah1, ah2, ah3,
                             Blo[nf][kf][0], Blo[nf][kf][1]);
                }
            }
        }
        __syncthreads();

        {
            float* rw = red + wid * RED_WSTRIDE;
#pragma unroll
            for (int mf = 0; mf < 2; ++mf) {
#pragma unroll
                for (int nf = 0; nf < 4; ++nf) {
                    int m = mf * 16 + g;
                    int n = nf * 8 + 2 * tg;
                    *reinterpret_cast<float2*>(&rw[m * RED_PITCH + n]) =
                        make_float2(acc[mf][nf][0], acc[mf][nf][1]);
                    *reinterpret_cast<float2*>(&rw[(m + 8) * RED_PITCH + n]) =
                        make_float2(acc[mf][nf][2], acc[mf][nf][3]);
                }
            }
        }
        __syncthreads();

        {
            int m  = tid >> 3;
            int nc = (tid & 7) * 4;
            float2 s0 = make_float2(0.f, 0.f);
            float2 s1 = make_float2(0.f, 0.f);
#pragma unroll
            for (int w = 0; w < 8; ++w) {
                const float* rw = red + w * RED_WSTRIDE + m * RED_PITCH + nc;
                float2 v0 = *reinterpret_cast<const float2*>(rw);
                float2 v1 = *reinterpret_cast<const float2*>(rw + 2);
                s0.x += v0.x; s0.y += v0.y;
                s1.x += v1.x; s1.y += v1.y;
            }
            float* p = buf + ((size_t)(b0 + m) * Tsz + t) * Hsz + n0 + nc;
            float4 q = *reinterpret_cast<float4*>(p);
            q.x = fmaxf(q.x + s0.x, 0.f);
            q.y = fmaxf(q.y + s0.y, 0.f);
            q.z = fmaxf(q.z + s1.x, 0.f);
            q.w = fmaxf(q.w + s1.y, 0.f);
            *reinterpret_cast<float4*>(p) = q;
        }

        if (t < Tsz - 1) flag_post(cta, (unsigned)(t + 1));
    }
}

// ---------------------------------------------------------------------------
// Final FC: out[b,c] = sum_i flat[b,i] * Wfc[c,i] + bfc[c]
// 64 CTAs; each handles 4 batch rows.
// ---------------------------------------------------------------------------
__global__ void __launch_bounds__(256) fc_kernel(
    const float* __restrict__ flat, const float* __restrict__ Wfc,
    const float* __restrict__ bfc, float* __restrict__ out)
{
    const int b = blockIdx.x;   // 0..63
    const float* xr[4];
#pragma unroll
    for (int rr = 0; rr < 4; ++rr)
        xr[rr] = flat + (size_t)(b + rr * 64) * (Tsz * Hsz);

    float acc[4][Csz];
#pragma unroll
    for (int rr = 0; rr < 4; ++rr)
#pragma unroll
        for (int c = 0; c < Csz; ++c) acc[rr][c] = 0.f;

    for (int i = threadIdx.x * 4; i < Tsz * Hsz; i += 256 * 4) {
        float4 x[4];
#pragma unroll
        for (int rr = 0; rr < 4; ++rr)
            x[rr] = *reinterpret_cast<const float4*>(xr[rr] + i);
#pragma unroll
        for (int c = 0; c < Csz; ++c) {
            float4 w = *reinterpret_cast<const float4*>(
                Wfc + (size_t)c * (Tsz * Hsz) + i);
#pragma unroll
            for (int rr = 0; rr < 4; ++rr)
                acc[rr][c] += x[rr].x * w.x + x[rr].y * w.y
                            + x[rr].z * w.z + x[rr].w * w.w;
        }
    }

#pragma unroll
    for (int rr = 0; rr < 4; ++rr)
#pragma unroll
        for (int c = 0; c < Csz; ++c)
#pragma unroll
            for (int off = 16; off > 0; off >>= 1)
                acc[rr][c] += __shfl_down_sync(0xffffffffu, acc[rr][c], off);

    __shared__ float part[4][Csz][8];
    const int warp = threadIdx.x >> 5;
    const int lane = threadIdx.x & 31;
    if (lane == 0) {
#pragma unroll
        for (int rr = 0; rr < 4; ++rr)
#pragma unroll
            for (int c = 0; c < Csz; ++c) part[rr][c][warp] = acc[rr][c];
    }
    __syncthreads();
    if (threadIdx.x < 4 * Csz) {
        int rr = threadIdx.x / Csz;
        int c  = threadIdx.x % Csz;
        float s = 0.f;
#pragma unroll
        for (int w = 0; w < 8; ++w) s += part[rr][c][w];
        out[(b + rr * 64) * Csz + c] = s + bfc[c];
    }
}

// ---------------------------------------------------------------------------
// kernel_launch: proj0 -> reset,rec0 -> proj1 -> reset,rec1 -> fc
// ---------------------------------------------------------------------------
extern "C" void kernel_launch(void* const* d_in, const int* in_sizes, int n_in,
                              void* d_out, int out_size)
{
    (void)in_sizes; (void)n_in; (void)out_size;
    const float* x     = (const float*)d_in[0];
    const float* W_ih0 = (const float*)d_in[1];
    const float* W_hh0 = (const float*)d_in[2];
    const float* b_ih0 = (const float*)d_in[3];
    const float* b_hh0 = (const float*)d_in[4];
    const float* W_ih1 = (const float*)d_in[5];
    const float* W_hh1 = (const float*)d_in[6];
    const float* b_ih1 = (const float*)d_in[7];
    const float* b_hh1 = (const float*)d_in[8];
    const float* W_fc  = (const float*)d_in[9];
    const float* b_fc  = (const float*)d_in[10];
    float* out = (float*)d_out;

    float* buf0 = nullptr;
    float* buf1 = nullptr;
    cudaGetSymbolAddress((void**)&buf0, g_buf0);
    cudaGetSymbolAddress((void**)&buf1, g_buf1);

    cudaFuncSetAttribute(rnn_rec_mma,
                         cudaFuncAttributeMaxDynamicSharedMemorySize,
                         REC_SMEM_BYTES);
    cudaFuncSetAttribute(proj_mma,
                         cudaFuncAttributeMaxDynamicSharedMemorySize,
                         PJ_SMEM_BYTES);

    dim3 pgrid(Hsz / 64, (Bsz * Tsz) / 128);   // (8, 256)

    // Layer 0
    proj_mma<<<pgrid, 256, PJ_SMEM_BYTES>>>(x, W_ih0, b_ih0, b_hh0, buf0, Fsz);
    reset_flags<<<1, 128>>>();
    rnn_rec_mma<<<REC_NBLK, 256, REC_SMEM_BYTES>>>(buf0, W_hh0);

    // Layer 1
    proj_mma<<<pgrid, 256, PJ_SMEM_BYTES>>>(buf0, W_ih1, b_ih1, b_hh1, buf1, Hsz);
    reset_flags<<<1, 128>>>();
    rnn_rec_mma<<<REC_NBLK, 256, REC_SMEM_BYTES>>>(buf1, W_hh1);

    // Classifier
    fc_kernel<<<64, 256>>>(buf1, W_fc, b_fc, out);
}

// round 14
// speedup vs baseline: 1.6907x; 1.1043x over previous
#include <cuda_runtime.h>
#include <cstdint>

#define Bsz 256
#define Tsz 128
#define Fsz 256
#define Hsz 512
#define Csz 10

// Scratch: proj/h buffers, written in place by the recurrence.
__device__ float g_buf0[Bsz * Tsz * Hsz];   // 64 MB
__device__ float g_buf1[Bsz * Tsz * Hsz];   // 64 MB

// Distributed barrier: one padded flag per CTA (128B apart).
#define REC_NBLK 128
__device__ unsigned g_flag[REC_NBLK * 32];

__global__ void reset_flags()
{
    if (threadIdx.x < REC_NBLK) g_flag[threadIdx.x * 32] = 0u;
}

// ---------------------------------------------------------------------------
// TF32 helpers (shared by recurrence and projection).
// ---------------------------------------------------------------------------
__device__ __forceinline__ uint32_t f2tf32(float x)
{
    uint32_t r;
    asm("cvt.rna.tf32.f32 %0, %1;" : "=r"(r) : "f"(x));
    return r;
}

__device__ __forceinline__ void mma_tf32(
    float& d0, float& d1, float& d2, float& d3,
    uint32_t a0, uint32_t a1, uint32_t a2, uint32_t a3,
    uint32_t b0, uint32_t b1)
{
    asm volatile(
        "mma.sync.aligned.m16n8k8.row.col.f32.tf32.tf32.f32 "
        "{%0,%1,%2,%3}, {%4,%5,%6,%7}, {%8,%9}, {%0,%1,%2,%3};\n"
        : "+f"(d0), "+f"(d1), "+f"(d2), "+f"(d3)
        : "r"(a0), "r"(a1), "r"(a2), "r"(a3), "r"(b0), "r"(b1));
}

// Split one fp32 smem value into tf32 hi (as reg) + lo (as tf32-able f32).
__device__ __forceinline__ void split_tf32(float v, uint32_t& hi, uint32_t& lo)
{
    hi = f2tf32(v);
    lo = __float_as_uint(v - __uint_as_float(hi));
}

// ---------------------------------------------------------------------------
// Tensor-core projection GEMM: out[m,n] = sum_k A[m,k]*Wt[n,k] + b1[n]+b2[n]
// M = 32768, N = 512, K in {256, 512}. 3xTF32 split (error ~2^-22).
// BM=128, BN=64, BK=32. 8 warps in 4m x 2n grid; warp tile 32x32.
// Single fp32 smem plane; hi/lo split done at fragment-load time (halves
// staging STS and fragment LDS crossbar traffic vs two-plane version).
// Smem pitch 36: bank = (4*row + k) mod 32 -> conflict-free.
// ---------------------------------------------------------------------------
#define PAP 36
#define PJS_B (128 * PAP)
#define PJ_SMEM_FLOATS (128 * PAP + 64 * PAP)
#define PJ_SMEM_BYTES (PJ_SMEM_FLOATS * 4)   // 27648 B

__global__ void __launch_bounds__(256, 2) proj_mma(
    const float* __restrict__ A, const float* __restrict__ Wt,
    const float* __restrict__ bias1, const float* __restrict__ bias2,
    float* __restrict__ out, int K)
{
    extern __shared__ float psm[];
    float* As = psm;
    float* Bs = psm + PJS_B;

    const int tid  = threadIdx.x;
    const int w    = tid >> 5;
    const int lane = tid & 31;
    const int wm   = w & 3;          // warp m-tile 0..3
    const int wn   = w >> 2;         // warp n-tile 0..1
    const int g    = lane >> 2;      // 0..7
    const int tg   = lane & 3;       // 0..3

    const int m0 = blockIdx.y * 128;
    const int n0 = blockIdx.x * 64;

    // Staging assignments (BK=32 floats per row per chunk).
    const int arow  = tid >> 1;           // 0..127
    const int apart = (tid & 1) * 16;     // two threads per A row
    const float* apg = A + (size_t)(m0 + arow) * K + apart;
    const int brow  = tid >> 2;           // 0..63
    const int bpart = (tid & 3) * 8;      // four threads per B row
    const float* bpg = Wt + (size_t)(n0 + brow) * K + bpart;

    float4 ra[4], rb[2];
#pragma unroll
    for (int u = 0; u < 4; ++u)
        ra[u] = *reinterpret_cast<const float4*>(apg + u * 4);
#pragma unroll
    for (int u = 0; u < 2; ++u)
        rb[u] = *reinterpret_cast<const float4*>(bpg + u * 4);

    float acc[2][4][4];
#pragma unroll
    for (int mf = 0; mf < 2; ++mf)
#pragma unroll
        for (int nf = 0; nf < 4; ++nf)
#pragma unroll
            for (int i = 0; i < 4; ++i) acc[mf][nf][i] = 0.f;

    const int S = K >> 5;
    for (int s = 0; s < S; ++s) {
        // Stage current chunk (raw fp32, no split here).
#pragma unroll
        for (int u = 0; u < 4; ++u)
            *reinterpret_cast<float4*>(&As[arow * PAP + apart + u * 4]) = ra[u];
#pragma unroll
        for (int u = 0; u < 2; ++u)
            *reinterpret_cast<float4*>(&Bs[brow * PAP + bpart + u * 4]) = rb[u];
        __syncthreads();

        // Prefetch next chunk while computing this one.
        if (s + 1 < S) {
            const size_t off = (size_t)(s + 1) * 32;
#pragma unroll
            for (int u = 0; u < 4; ++u)
                ra[u] = *reinterpret_cast<const float4*>(apg + off + u * 4);
#pragma unroll
            for (int u = 0; u < 2; ++u)
                rb[u] = *reinterpret_cast<const float4*>(bpg + off + u * 4);
        }

#pragma unroll
        for (int kf = 0; kf < 4; ++kf) {
            uint32_t ah[2][4], al[2][4];
#pragma unroll
            for (int mf = 0; mf < 2; ++mf) {
                const int o = (wm * 32 + mf * 16 + g) * PAP + kf * 8 + tg;
                split_tf32(As[o],               ah[mf][0], al[mf][0]);
                split_tf32(As[o + 8 * PAP],     ah[mf][1], al[mf][1]);
                split_tf32(As[o + 4],           ah[mf][2], al[mf][2]);
                split_tf32(As[o + 8 * PAP + 4], ah[mf][3], al[mf][3]);
            }
            uint32_t bh[4][2], bl[4][2];
#pragma unroll
            for (int nf = 0; nf < 4; ++nf) {
                const int o = (wn * 32 + nf * 8 + g) * PAP + kf * 8 + tg;
                split_tf32(Bs[o],     bh[nf][0], bl[nf][0]);
                split_tf32(Bs[o + 4], bh[nf][1], bl[nf][1]);
            }
#pragma unroll
            for (int mf = 0; mf < 2; ++mf) {
#pragma unroll
                for (int nf = 0; nf < 4; ++nf) {
                    mma_tf32(acc[mf][nf][0], acc[mf][nf][1],
                             acc[mf][nf][2], acc[mf][nf][3],
                             ah[mf][0], ah[mf][1], ah[mf][2], ah[mf][3],
                             bh[nf][0], bh[nf][1]);
                    mma_tf32(acc[mf][nf][0], acc[mf][nf][1],
                             acc[mf][nf][2], acc[mf][nf][3],
                             al[mf][0], al[mf][1], al[mf][2], al[mf][3],
                             bh[nf][0], bh[nf][1]);
                    mma_tf32(acc[mf][nf][0], acc[mf][nf][1],
                             acc[mf][nf][2], acc[mf][nf][3],
                             ah[mf][0], ah[mf][1], ah[mf][2], ah[mf][3],
                             bl[nf][0], bl[nf][1]);
                }
            }
        }
        __syncthreads();
    }

    // Epilogue: add biases, write fp32.
#pragma unroll
    for (int nf = 0; nf < 4; ++nf) {
        const int n = n0 + wn * 32 + nf * 8 + 2 * tg;
        const float b0 = bias1[n] + bias2[n];
        const float b1 = bias1[n + 1] + bias2[n + 1];
#pragma unroll
        for (int mf = 0; mf < 2; ++mf) {
            const int m = m0 + wm * 32 + mf * 16 + g;
            *reinterpret_cast<float2*>(&out[(size_t)m * Hsz + n]) =
                make_float2(acc[mf][nf][0] + b0, acc[mf][nf][1] + b1);
            *reinterpret_cast<float2*>(&out[(size_t)(m + 8) * Hsz + n]) =
                make_float2(acc[mf][nf][2] + b0, acc[mf][nf][3] + b1);
        }
    }
}

// ---------------------------------------------------------------------------
// Distributed-flag barrier primitives (group-local: batch-row groups are
// independent, so CTA (m,n) waits only on the 16 CTAs sharing tile_m).
// ---------------------------------------------------------------------------
__device__ __forceinline__ void flag_post(int cta, unsigned val)
{
    __syncthreads();
    if (threadIdx.x == 0) {
        __threadfence();             // release
        *(volatile unsigned*)&g_flag[cta * 32] = val;
    }
}

__device__ __forceinline__ void flag_wait_group(int group, unsigned val)
{
    if (threadIdx.x < 16) {
        const int peer = group * 16 + threadIdx.x;
        while (*(volatile unsigned*)&g_flag[peer * 32] < val) { }
        __threadfence();             // acquire
    }
    __syncthreads();
}

// ---------------------------------------------------------------------------
// Tensor-core recurrence (both layers). Same validated structure as R12/R13,
// with: (a) group-local waits, (b) dedicated reduction buffer so the
// post-MMA syncthreads before partial stores is gone (own-region writes).
// ---------------------------------------------------------------------------
#define REC_AP 516
#define RED_PITCH 34
#define RED_WSTRIDE (32 * RED_PITCH)
#define REC_SMEM_FLOATS (2 * 32 * REC_AP + 8 * RED_WSTRIDE)
#define REC_SMEM_BYTES (REC_SMEM_FLOATS * 4)    // 166912 B

__global__ void __launch_bounds__(256) rnn_rec_mma(
    float* __restrict__ buf, const float* __restrict__ Whh)
{
    extern __shared__ float sm[];
    float* Ahi = sm;                      // [32][REC_AP]
    float* Alo = sm + 32 * REC_AP;        // [32][REC_AP]
    float* red = sm + 2 * 32 * REC_AP;    // [8][RED_WSTRIDE] (dedicated)

    const int tid  = threadIdx.x;
    const int cta  = blockIdx.x;
    const int wid  = tid >> 5;
    const int lane = tid & 31;
    const int g    = lane >> 2;
    const int tg   = lane & 3;

    const int tile_m = cta >> 4;
    const int tile_n = cta & 15;
    const int b0 = tile_m * 32;
    const int n0 = tile_n * 32;

    uint32_t Bhi[4][8][2], Blo[4][8][2];
#pragma unroll
    for (int nf = 0; nf < 4; ++nf) {
#pragma unroll
        for (int kf = 0; kf < 8; ++kf) {
            const float* wp = Whh + (size_t)(n0 + nf * 8 + g) * Hsz
                            + wid * 64 + kf * 8 + tg;
            float w0 = wp[0];
            float w1 = wp[4];
            uint32_t h0 = f2tf32(w0);
            uint32_t h1 = f2tf32(w1);
            Bhi[nf][kf][0] = h0;
            Bhi[nf][kf][1] = h1;
            Blo[nf][kf][0] = f2tf32(w0 - __uint_as_float(h0));
            Blo[nf][kf][1] = f2tf32(w1 - __uint_as_float(h1));
        }
    }

    for (int i = tid; i < 32 * 32; i += 256) {
        int rr = i >> 5;
        int c  = i & 31;
        float* p = buf + ((size_t)(b0 + rr) * Tsz + 0) * Hsz + n0 + c;
        *p = fmaxf(*p, 0.f);
    }
    flag_post(cta, 1u);

    const int abase = g * REC_AP + wid * 64 + tg;

    for (int t = 1; t < Tsz; ++t) {
        flag_wait_group(tile_m, (unsigned)t);

        // Stage h_{t-1} rows of this batch group into smem (tf32 hi/lo).
        for (int i = tid; i < 32 * 128; i += 256) {
            int rr = i >> 7;
            int c  = (i & 127) * 4;
            float4 v = *reinterpret_cast<const float4*>(
                buf + ((size_t)(b0 + rr) * Tsz + (t - 1)) * Hsz + c);
            uint32_t hx = f2tf32(v.x), hy = f2tf32(v.y),
                     hz = f2tf32(v.z), hw = f2tf32(v.w);
            float4 hi4 = make_float4(__uint_as_float(hx), __uint_as_float(hy),
                                     __uint_as_float(hz), __uint_as_float(hw));
            float4 lo4 = make_float4(v.x - hi4.x, v.y - hi4.y,
                                     v.z - hi4.z, v.w - hi4.w);
            *reinterpret_cast<float4*>(Ahi + rr * REC_AP + c) = hi4;
            *reinterpret_cast<float4*>(Alo + rr * REC_AP + c) = lo4;
        }
        __syncthreads();

        float acc[2][4][4];
#pragma unroll
        for (int mf = 0; mf < 2; ++mf)
#pragma unroll
            for (int nf = 0; nf < 4; ++nf)
#pragma unroll
                for (int i = 0; i < 4; ++i) acc[mf][nf][i] = 0.f;

        const uint32_t* AhiU = reinterpret_cast<const uint32_t*>(Ahi);
        const uint32_t* AloU = reinterpret_cast<const uint32_t*>(Alo);

#pragma unroll
        for (int kf = 0; kf < 8; ++kf) {
#pragma unroll
            for (int mf = 0; mf < 2; ++mf) {
                const int off = abase + kf * 8 + mf * (16 * REC_AP);
                uint32_t ah0 = AhiU[off];
                uint32_t ah1 = AhiU[off + 8 * REC_AP];
                uint32_t ah2 = AhiU[off + 4];
                uint32_t ah3 = AhiU[off + 8 * REC_AP + 4];
                uint32_t al0 = AloU[off];
                uint32_t al1 = AloU[off + 8 * REC_AP];
                uint32_t al2 = AloU[off + 4];
                uint32_t al3 = AloU[off + 8 * REC_AP + 4];
#pragma unroll
                for (int nf = 0; nf < 4; ++nf) {
                    mma_tf32(acc[mf][nf][0], acc[mf][nf][1],
                             acc[mf][nf][2], acc[mf][nf][3],
                             ah0, ah1, ah2, ah3,
                             Bhi[nf][kf][0], Bhi[nf][kf][1]);
                    mma_tf32(acc[mf][nf][0], acc[mf][nf][1],
                             acc[mf][nf][2], acc[mf][nf][3],
                             al0, al1, al2, al3,
                             Bhi[nf][kf][0], Bhi[nf][kf][1]);
                    mma_tf32(acc[mf][nf][0], acc[mf][nf][1],
                             acc[mf][nf][2], acc[mf][nf][3],
                             ah0, ah1, ah2, ah3,
                             Blo[nf][kf][0], Blo[nf][kf][1]);
                }
            }
        }

        // Partial stores to this warp's OWN red region — no sync needed
        // between MMA and these (red no longer aliases Ahi/Alo).
        {
            float* rw = red + wid * RED_WSTRIDE;
#pragma unroll
            for (int mf = 0; mf < 2; ++mf) {
#pragma unroll
                for (int nf = 0; nf < 4; ++nf) {
                    int m = mf * 16 + g;
                    int n = nf * 8 + 2 * tg;
                    *reinterpret_cast<float2*>(&rw[m * RED_PITCH + n]) =
                        make_float2(acc[mf][nf][0], acc[mf][nf][1]);
                    *reinterpret_cast<float2*>(&rw[(m + 8) * RED_PITCH + n]) =
                        make_float2(acc[mf][nf][2], acc[mf][nf][3]);
                }
            }
        }
        __syncthreads();

        // Reduce 8 warps' partials; h_t = relu(proj_t + sum), in place.
        {
            int m  = tid >> 3;
            int nc = (tid & 7) * 4;
            float2 s0 = make_float2(0.f, 0.f);
            float2 s1 = make_float2(0.f, 0.f);
#pragma unroll
            for (int w = 0; w < 8; ++w) {
                const float* rw = red + w * RED_WSTRIDE + m * RED_PITCH + nc;
                float2 v0 = *reinterpret_cast<const float2*>(rw);
                float2 v1 = *reinterpret_cast<const float2*>(rw + 2);
                s0.x += v0.x; s0.y += v0.y;
                s1.x += v1.x; s1.y += v1.y;
            }
            float* p = buf + ((size_t)(b0 + m) * Tsz + t) * Hsz + n0 + nc;
            float4 q = *reinterpret_cast<float4*>(p);
            q.x = fmaxf(q.x + s0.x, 0.f);
            q.y = fmaxf(q.y + s0.y, 0.f);
            q.z = fmaxf(q.z + s1.x, 0.f);
            q.w = fmaxf(q.w + s1.y, 0.f);
            *reinterpret_cast<float4*>(p) = q;
        }

        if (t < Tsz - 1) flag_post(cta, (unsigned)(t + 1));
    }
}

// ---------------------------------------------------------------------------
// Final FC: out[b,c] = sum_i flat[b,i] * Wfc[c,i] + bfc[c]
// 64 CTAs; each handles 4 batch rows.
// ---------------------------------------------------------------------------
__global__ void __launch_bounds__(256) fc_kernel(
    const float* __restrict__ flat, const float* __restrict__ Wfc,
    const float* __restrict__ bfc, float* __restrict__ out)
{
    const int b = blockIdx.x;   // 0..63
    const float* xr[4];
#pragma unroll
    for (int rr = 0; rr < 4; ++rr)
        xr[rr] = flat + (size_t)(b + rr * 64) * (Tsz * Hsz);

    float acc[4][Csz];
#pragma unroll
    for (int rr = 0; rr < 4; ++rr)
#pragma unroll
        for (int c = 0; c < Csz; ++c) acc[rr][c] = 0.f;

    for (int i = threadIdx.x * 4; i < Tsz * Hsz; i += 256 * 4) {
        float4 x[4];
#pragma unroll
        for (int rr = 0; rr < 4; ++rr)
            x[rr] = *reinterpret_cast<const float4*>(xr[rr] + i);
#pragma unroll
        for (int c = 0; c < Csz; ++c) {
            float4 w = *reinterpret_cast<const float4*>(
                Wfc + (size_t)c * (Tsz * Hsz) + i);
#pragma unroll
            for (int rr = 0; rr < 4; ++rr)
                acc[rr][c] += x[rr].x * w.x + x[rr].y * w.y
                            + x[rr].z * w.z + x[rr].w * w.w;
        }
    }

#pragma unroll
    for (int rr = 0; rr < 4; ++rr)
#pragma unroll
        for (int c = 0; c < Csz; ++c)
#pragma unroll
            for (int off = 16; off > 0; off >>= 1)
                acc[rr][c] += __shfl_down_sync(0xffffffffu, acc[rr][c], off);

    __shared__ float part[4][Csz][8];
    const int warp = threadIdx.x >> 5;
    const int lane = threadIdx.x & 31;
    if (lane == 0) {
#pragma unroll
        for (int rr = 0; rr < 4; ++rr)
#pragma unroll
            for (int c = 0; c < Csz; ++c) part[rr][c][warp] = acc[rr][c];
    }
    __syncthreads();
    if (threadIdx.x < 4 * Csz) {
        int rr = threadIdx.x / Csz;
        int c  = threadIdx.x % Csz;
        float s = 0.f;
#pragma unroll
        for (int w = 0; w < 8; ++w) s += part[rr][c][w];
        out[(b + rr * 64) * Csz + c] = s + bfc[c];
    }
}

// ---------------------------------------------------------------------------
// kernel_launch: proj0 -> reset,rec0 -> proj1 -> reset,rec1 -> fc
// ---------------------------------------------------------------------------
extern "C" void kernel_launch(void* const* d_in, const int* in_sizes, int n_in,
                              void* d_out, int out_size)
{
    (void)in_sizes; (void)n_in; (void)out_size;
    const float* x     = (const float*)d_in[0];
    const float* W_ih0 = (const float*)d_in[1];
    const float* W_hh0 = (const float*)d_in[2];
    const float* b_ih0 = (const float*)d_in[3];
    const float* b_hh0 = (const float*)d_in[4];
    const float* W_ih1 = (const float*)d_in[5];
    const float* W_hh1 = (const float*)d_in[6];
    const float* b_ih1 = (const float*)d_in[7];
    const float* b_hh1 = (const float*)d_in[8];
    const float* W_fc  = (const float*)d_in[9];
    const float* b_fc  = (const float*)d_in[10];
    float* out = (float*)d_out;

    float* buf0 = nullptr;
    float* buf1 = nullptr;
    cudaGetSymbolAddress((void**)&buf0, g_buf0);
    cudaGetSymbolAddress((void**)&buf1, g_buf1);

    cudaFuncSetAttribute(rnn_rec_mma,
                         cudaFuncAttributeMaxDynamicSharedMemorySize,
                         REC_SMEM_BYTES);
    cudaFuncSetAttribute(proj_mma,
                         cudaFuncAttributeMaxDynamicSharedMemorySize,
                         PJ_SMEM_BYTES);

    dim3 pgrid(Hsz / 64, (Bsz * Tsz) / 128);   // (8, 256)

    // Layer 0
    proj_mma<<<pgrid, 256, PJ_SMEM_BYTES>>>(x, W_ih0, b_ih0, b_hh0, buf0, Fsz);
    reset_flags<<<1, 128>>>();
    rnn_rec_mma<<<REC_NBLK, 256, REC_SMEM_BYTES>>>(buf0, W_hh0);

    // Layer 1
    proj_mma<<<pgrid, 256, PJ_SMEM_BYTES>>>(buf0, W_ih1, b_ih1, b_hh1, buf1, Hsz);
    reset_flags<<<1, 128>>>();
    rnn_rec_mma<<<REC_NBLK, 256, REC_SMEM_BYTES>>>(buf1, W_hh1);

    // Classifier
    fc_kernel<<<64, 256>>>(buf1, W_fc, b_fc, out);
}

// round 15
// speedup vs baseline: 1.9150x; 1.1326x over previous
#include <cuda_runtime.h>
#include <cstdint>

#define Bsz 256
#define Tsz 128
#define Fsz 256
#define Hsz 512
#define Csz 10

// Scratch: proj/h buffers, written in place by the recurrence.
__device__ float g_buf0[Bsz * Tsz * Hsz];   // 64 MB
__device__ float g_buf1[Bsz * Tsz * Hsz];   // 64 MB

// Distributed barrier: one padded flag per CTA (128B apart).
#define REC_NBLK 128
__device__ unsigned g_flag[REC_NBLK * 32];

__global__ void reset_flags()
{
    if (threadIdx.x < REC_NBLK) g_flag[threadIdx.x * 32] = 0u;
}

// ---------------------------------------------------------------------------
// TF32 helpers (shared by recurrence and projection).
// ---------------------------------------------------------------------------
__device__ __forceinline__ uint32_t f2tf32(float x)
{
    uint32_t r;
    asm("cvt.rna.tf32.f32 %0, %1;" : "=r"(r) : "f"(x));
    return r;
}

__device__ __forceinline__ void mma_tf32(
    float& d0, float& d1, float& d2, float& d3,
    uint32_t a0, uint32_t a1, uint32_t a2, uint32_t a3,
    uint32_t b0, uint32_t b1)
{
    asm volatile(
        "mma.sync.aligned.m16n8k8.row.col.f32.tf32.tf32.f32 "
        "{%0,%1,%2,%3}, {%4,%5,%6,%7}, {%8,%9}, {%0,%1,%2,%3};\n"
        : "+f"(d0), "+f"(d1), "+f"(d2), "+f"(d3)
        : "r"(a0), "r"(a1), "r"(a2), "r"(a3), "r"(b0), "r"(b1));
}

// Split one fp32 value into tf32 hi + lo residual (as tf32-able f32).
__device__ __forceinline__ void split_tf32(float v, uint32_t& hi, uint32_t& lo)
{
    hi = f2tf32(v);
    lo = __float_as_uint(v - __uint_as_float(hi));
}

// ---------------------------------------------------------------------------
// Tensor-core projection GEMM (unchanged from R14 — passing, tensor 60.5%).
// out[m,n] = sum_k A[m,k]*Wt[n,k] + b1[n]+b2[n]. 3xTF32 split.
// ---------------------------------------------------------------------------
#define PAP 36
#define PJS_B (128 * PAP)
#define PJ_SMEM_FLOATS (128 * PAP + 64 * PAP)
#define PJ_SMEM_BYTES (PJ_SMEM_FLOATS * 4)   // 27648 B

__global__ void __launch_bounds__(256, 2) proj_mma(
    const float* __restrict__ A, const float* __restrict__ Wt,
    const float* __restrict__ bias1, const float* __restrict__ bias2,
    float* __restrict__ out, int K)
{
    extern __shared__ float psm[];
    float* As = psm;
    float* Bs = psm + PJS_B;

    const int tid  = threadIdx.x;
    const int w    = tid >> 5;
    const int lane = tid & 31;
    const int wm   = w & 3;
    const int wn   = w >> 2;
    const int g    = lane >> 2;
    const int tg   = lane & 3;

    const int m0 = blockIdx.y * 128;
    const int n0 = blockIdx.x * 64;

    const int arow  = tid >> 1;
    const int apart = (tid & 1) * 16;
    const float* apg = A + (size_t)(m0 + arow) * K + apart;
    const int brow  = tid >> 2;
    const int bpart = (tid & 3) * 8;
    const float* bpg = Wt + (size_t)(n0 + brow) * K + bpart;

    float4 ra[4], rb[2];
#pragma unroll
    for (int u = 0; u < 4; ++u)
        ra[u] = *reinterpret_cast<const float4*>(apg + u * 4);
#pragma unroll
    for (int u = 0; u < 2; ++u)
        rb[u] = *reinterpret_cast<const float4*>(bpg + u * 4);

    float acc[2][4][4];
#pragma unroll
    for (int mf = 0; mf < 2; ++mf)
#pragma unroll
        for (int nf = 0; nf < 4; ++nf)
#pragma unroll
            for (int i = 0; i < 4; ++i) acc[mf][nf][i] = 0.f;

    const int S = K >> 5;
    for (int s = 0; s < S; ++s) {
#pragma unroll
        for (int u = 0; u < 4; ++u)
            *reinterpret_cast<float4*>(&As[arow * PAP + apart + u * 4]) = ra[u];
#pragma unroll
        for (int u = 0; u < 2; ++u)
            *reinterpret_cast<float4*>(&Bs[brow * PAP + bpart + u * 4]) = rb[u];
        __syncthreads();

        if (s + 1 < S) {
            const size_t off = (size_t)(s + 1) * 32;
#pragma unroll
            for (int u = 0; u < 4; ++u)
                ra[u] = *reinterpret_cast<const float4*>(apg + off + u * 4);
#pragma unroll
            for (int u = 0; u < 2; ++u)
                rb[u] = *reinterpret_cast<const float4*>(bpg + off + u * 4);
        }

#pragma unroll
        for (int kf = 0; kf < 4; ++kf) {
            uint32_t ah[2][4], al[2][4];
#pragma unroll
            for (int mf = 0; mf < 2; ++mf) {
                const int o = (wm * 32 + mf * 16 + g) * PAP + kf * 8 + tg;
                split_tf32(As[o],               ah[mf][0], al[mf][0]);
                split_tf32(As[o + 8 * PAP],     ah[mf][1], al[mf][1]);
                split_tf32(As[o + 4],           ah[mf][2], al[mf][2]);
                split_tf32(As[o + 8 * PAP + 4], ah[mf][3], al[mf][3]);
            }
            uint32_t bh[4][2], bl[4][2];
#pragma unroll
            for (int nf = 0; nf < 4; ++nf) {
                const int o = (wn * 32 + nf * 8 + g) * PAP + kf * 8 + tg;
                split_tf32(Bs[o],     bh[nf][0], bl[nf][0]);
                split_tf32(Bs[o + 4], bh[nf][1], bl[nf][1]);
            }
#pragma unroll
            for (int mf = 0; mf < 2; ++mf) {
#pragma unroll
                for (int nf = 0; nf < 4; ++nf) {
                    mma_tf32(acc[mf][nf][0], acc[mf][nf][1],
                             acc[mf][nf][2], acc[mf][nf][3],
                             ah[mf][0], ah[mf][1], ah[mf][2], ah[mf][3],
                             bh[nf][0], bh[nf][1]);
                    mma_tf32(acc[mf][nf][0], acc[mf][nf][1],
                             acc[mf][nf][2], acc[mf][nf][3],
                             al[mf][0], al[mf][1], al[mf][2], al[mf][3],
                             bh[nf][0], bh[nf][1]);
                    mma_tf32(acc[mf][nf][0], acc[mf][nf][1],
                             acc[mf][nf][2], acc[mf][nf][3],
                             ah[mf][0], ah[mf][1], ah[mf][2], ah[mf][3],
                             bl[nf][0], bl[nf][1]);
                }
            }
        }
        __syncthreads();
    }

#pragma unroll
    for (int nf = 0; nf < 4; ++nf) {
        const int n = n0 + wn * 32 + nf * 8 + 2 * tg;
        const float b0 = bias1[n] + bias2[n];
        const float b1 = bias1[n + 1] + bias2[n + 1];
#pragma unroll
        for (int mf = 0; mf < 2; ++mf) {
            const int m = m0 + wm * 32 + mf * 16 + g;
            *reinterpret_cast<float2*>(&out[(size_t)m * Hsz + n]) =
                make_float2(acc[mf][nf][0] + b0, acc[mf][nf][1] + b1);
            *reinterpret_cast<float2*>(&out[(size_t)(m + 8) * Hsz + n]) =
                make_float2(acc[mf][nf][2] + b0, acc[mf][nf][3] + b1);
        }
    }
}

// ---------------------------------------------------------------------------
// Flag post (block-wide: all this CTA's h_t writes are published).
// ---------------------------------------------------------------------------
__device__ __forceinline__ void flag_post(int cta, unsigned val)
{
    __syncthreads();                 // also protects red reuse across steps
    if (threadIdx.x == 0) {
        __threadfence();             // release
        *(volatile unsigned*)&g_flag[cta * 32] = val;
    }
}

// ---------------------------------------------------------------------------
// Tensor-core recurrence with WARP-LEVEL dataflow sync.
// 128 CTAs x 256 threads. CTA tile: 32 batch rows x 32 hidden cols.
// Warp w owns k-slice [64w, 64w+64) whose h-data is produced by exactly the
// 2 CTAs (tile_m, 2w) and (tile_m, 2w+1). Each warp independently:
//   poll its 2 producer flags -> stage its own 8KB raw-fp32 slice ->
//   syncwarp -> MMA (split to tf32 hi/lo at frag load).
// Block-wide sync only before the cross-warp k-reduction.
// ---------------------------------------------------------------------------
#define REC_AP 516
#define RED_PITCH 34
#define RED_WSTRIDE (32 * RED_PITCH)
#define REC_SMEM_FLOATS (32 * REC_AP + 8 * RED_WSTRIDE)
#define REC_SMEM_BYTES (REC_SMEM_FLOATS * 4)    // 100864 B

__global__ void __launch_bounds__(256) rnn_rec_mma(
    float* __restrict__ buf, const float* __restrict__ Whh)
{
    extern __shared__ float sm[];
    float* As  = sm;                  // [32][REC_AP] raw fp32 h_{t-1}
    float* red = sm + 32 * REC_AP;    // [8][RED_WSTRIDE]

    const int tid  = threadIdx.x;
    const int cta  = blockIdx.x;
    const int wid  = tid >> 5;
    const int lane = tid & 31;
    const int g    = lane >> 2;
    const int tg   = lane & 3;

    const int tile_m = cta >> 4;
    const int tile_n = cta & 15;
    const int b0 = tile_m * 32;
    const int n0 = tile_n * 32;

    // W_hh fragments (hi/lo) in registers for all steps; warp wid owns
    // k in [64*wid, 64*wid+64).
    uint32_t Bhi[4][8][2], Blo[4][8][2];
#pragma unroll
    for (int nf = 0; nf < 4; ++nf) {
#pragma unroll
        for (int kf = 0; kf < 8; ++kf) {
            const float* wp = Whh + (size_t)(n0 + nf * 8 + g) * Hsz
                            + wid * 64 + kf * 8 + tg;
            float w0 = wp[0];
            float w1 = wp[4];
            uint32_t h0 = f2tf32(w0);
            uint32_t h1 = f2tf32(w1);
            Bhi[nf][kf][0] = h0;
            Bhi[nf][kf][1] = h1;
            Blo[nf][kf][0] = f2tf32(w0 - __uint_as_float(h0));
            Blo[nf][kf][1] = f2tf32(w1 - __uint_as_float(h1));
        }
    }

    // t = 0: h_0 = relu(proj_0)
    for (int i = tid; i < 32 * 32; i += 256) {
        int rr = i >> 5;
        int c  = i & 31;
        float* p = buf + ((size_t)(b0 + rr) * Tsz + 0) * Hsz + n0 + c;
        *p = fmaxf(*p, 0.f);
    }
    flag_post(cta, 1u);

    // This warp's 2 producers (per-lane poll target).
    const int prod = (tile_m * 16 + wid * 2 + (lane & 1)) * 32;
    const int abase = g * REC_AP + wid * 64 + tg;

    for (int t = 1; t < Tsz; ++t) {
        // -- Warp-local wait: only this warp's 2 producers must be done. --
        while (*(volatile unsigned*)&g_flag[prod] < (unsigned)t) { }
        __threadfence();             // per-lane acquire
        __syncwarp();

        // -- Stage this warp's own 8KB k-slice (raw fp32). --
        {
            const float* src = buf + ((size_t)b0 * Tsz + (t - 1)) * Hsz
                             + wid * 64;
            float* dst = As + wid * 64;
#pragma unroll
            for (int i = 0; i < 16; ++i) {
                int idx = i * 32 + lane;          // 0..511
                int rr = idx >> 4;                // 0..31
                int c  = (idx & 15) * 4;          // 0..60
                float4 v = *reinterpret_cast<const float4*>(
                    src + (size_t)rr * (Tsz * Hsz) + c);
                *reinterpret_cast<float4*>(dst + rr * REC_AP + c) = v;
            }
        }
        __syncwarp();

        // -- MMA over this warp's k-slice; split to hi/lo at frag load. --
        float acc[2][4][4];
#pragma unroll
        for (int mf = 0; mf < 2; ++mf)
#pragma unroll
            for (int nf = 0; nf < 4; ++nf)
#pragma unroll
                for (int i = 0; i < 4; ++i) acc[mf][nf][i] = 0.f;

#pragma unroll
        for (int kf = 0; kf < 8; ++kf) {
#pragma unroll
            for (int mf = 0; mf < 2; ++mf) {
                const int off = abase + kf * 8 + mf * (16 * REC_AP);
                uint32_t ah0, ah1, ah2, ah3, al0, al1, al2, al3;
                split_tf32(As[off],                  ah0, al0);
                split_tf32(As[off + 8 * REC_AP],     ah1, al1);
                split_tf32(As[off + 4],              ah2, al2);
                split_tf32(As[off + 8 * REC_AP + 4], ah3, al3);
#pragma unroll
                for (int nf = 0; nf < 4; ++nf) {
                    mma_tf32(acc[mf][nf][0], acc[mf][nf][1],
                             acc[mf][nf][2], acc[mf][nf][3],
                             ah0, ah1, ah2, ah3,
                             Bhi[nf][kf][0], Bhi[nf][kf][1]);
                    mma_tf32(acc[mf][nf][0], acc[mf][nf][1],
                             acc[mf][nf][2], acc[mf][nf][3],
                             al0, al1, al2, al3,
                             Bhi[nf][kf][0], Bhi[nf][kf][1]);
                    mma_tf32(acc[mf][nf][0], acc[mf][nf][1],
                             acc[mf][nf][2], acc[mf][nf][3],
                             ah0, ah1, ah2, ah3,
                             Blo[nf][kf][0], Blo[nf][kf][1]);
                }
            }
        }

        // -- Partial stores to this warp's own red region. --
        {
            float* rw = red + wid * RED_WSTRIDE;
#pragma unroll
            for (int mf = 0; mf < 2; ++mf) {
#pragma unroll
                for (int nf = 0; nf < 4; ++nf) {
                    int m = mf * 16 + g;
                    int n = nf * 8 + 2 * tg;
                    *reinterpret_cast<float2*>(&rw[m * RED_PITCH + n]) =
                        make_float2(acc[mf][nf][0], acc[mf][nf][1]);
                    *reinterpret_cast<float2*>(&rw[(m + 8) * RED_PITCH + n]) =
                        make_float2(acc[mf][nf][2], acc[mf][nf][3]);
                }
            }
        }
        __syncthreads();   // all warps' partials visible

        // -- Reduce 8 warps' partials; h_t = relu(proj_t + sum), in place. --
        {
            int m  = tid >> 3;
            int nc = (tid & 7) * 4;
            float2 s0 = make_float2(0.f, 0.f);
            float2 s1 = make_float2(0.f, 0.f);
#pragma unroll
            for (int w = 0; w < 8; ++w) {
                const float* rw = red + w * RED_WSTRIDE + m * RED_PITCH + nc;
                float2 v0 = *reinterpret_cast<const float2*>(rw);
                float2 v1 = *reinterpret_cast<const float2*>(rw + 2);
                s0.x += v0.x; s0.y += v0.y;
                s1.x += v1.x; s1.y += v1.y;
            }
            float* p = buf + ((size_t)(b0 + m) * Tsz + t) * Hsz + n0 + nc;
            float4 q = *reinterpret_cast<float4*>(p);
            q.x = fmaxf(q.x + s0.x, 0.f);
            q.y = fmaxf(q.y + s0.y, 0.f);
            q.z = fmaxf(q.z + s1.x, 0.f);
            q.w = fmaxf(q.w + s1.y, 0.f);
            *reinterpret_cast<float4*>(p) = q;
        }

        if (t < Tsz - 1) flag_post(cta, (unsigned)(t + 1));
        else __syncthreads();   // red-reuse guard not needed, but cheap exit
    }
}

// ---------------------------------------------------------------------------
// Final FC: out[b,c] = sum_i flat[b,i] * Wfc[c,i] + bfc[c]
// 64 CTAs; each handles 4 batch rows.
// ---------------------------------------------------------------------------
__global__ void __launch_bounds__(256) fc_kernel(
    const float* __restrict__ flat, const float* __restrict__ Wfc,
    const float* __restrict__ bfc, float* __restrict__ out)
{
    const int b = blockIdx.x;   // 0..63
    const float* xr[4];
#pragma unroll
    for (int rr = 0; rr < 4; ++rr)
        xr[rr] = flat + (size_t)(b + rr * 64) * (Tsz * Hsz);

    float acc[4][Csz];
#pragma unroll
    for (int rr = 0; rr < 4; ++rr)
#pragma unroll
        for (int c = 0; c < Csz; ++c) acc[rr][c] = 0.f;

    for (int i = threadIdx.x * 4; i < Tsz * Hsz; i += 256 * 4) {
        float4 x[4];
#pragma unroll
        for (int rr = 0; rr < 4; ++rr)
            x[rr] = *reinterpret_cast<const float4*>(xr[rr] + i);
#pragma unroll
        for (int c = 0; c < Csz; ++c) {
            float4 w = *reinterpret_cast<const float4*>(
                Wfc + (size_t)c * (Tsz * Hsz) + i);
#pragma unroll
            for (int rr = 0; rr < 4; ++rr)
                acc[rr][c] += x[rr].x * w.x + x[rr].y * w.y
                            + x[rr].z * w.z + x[rr].w * w.w;
        }
    }

#pragma unroll
    for (int rr = 0; rr < 4; ++rr)
#pragma unroll
        for (int c = 0; c < Csz; ++c)
#pragma unroll
            for (int off = 16; off > 0; off >>= 1)
                acc[rr][c] += __shfl_down_sync(0xffffffffu, acc[rr][c], off);

    __shared__ float part[4][Csz][8];
    const int warp = threadIdx.x >> 5;
    const int lane = threadIdx.x & 31;
    if (lane == 0) {
#pragma unroll
        for (int rr = 0; rr < 4; ++rr)
#pragma unroll
            for (int c = 0; c < Csz; ++c) part[rr][c][warp] = acc[rr][c];
    }
    __syncthreads();
    if (threadIdx.x < 4 * Csz) {
        int rr = threadIdx.x / Csz;
        int c  = threadIdx.x % Csz;
        float s = 0.f;
#pragma unroll
        for (int w = 0; w < 8; ++w) s += part[rr][c][w];
        out[(b + rr * 64) * Csz + c] = s + bfc[c];
    }
}

// ---------------------------------------------------------------------------
// kernel_launch: proj0 -> reset,rec0 -> proj1 -> reset,rec1 -> fc
// ---------------------------------------------------------------------------
extern "C" void kernel_launch(void* const* d_in, const int* in_sizes, int n_in,
                              void* d_out, int out_size)
{
    (void)in_sizes; (void)n_in; (void)out_size;
    const float* x     = (const float*)d_in[0];
    const float* W_ih0 = (const float*)d_in[1];
    const float* W_hh0 = (const float*)d_in[2];
    const float* b_ih0 = (const float*)d_in[3];
    const float* b_hh0 = (const float*)d_in[4];
    const float* W_ih1 = (const float*)d_in[5];
    const float* W_hh1 = (const float*)d_in[6];
    const float* b_ih1 = (const float*)d_in[7];
    const float* b_hh1 = (const float*)d_in[8];
    const float* W_fc  = (const float*)d_in[9];
    const float* b_fc  = (const float*)d_in[10];
    float* out = (float*)d_out;

    float* buf0 = nullptr;
    float* buf1 = nullptr;
    cudaGetSymbolAddress((void**)&buf0, g_buf0);
    cudaGetSymbolAddress((void**)&buf1, g_buf1);

    cudaFuncSetAttribute(rnn_rec_mma,
                         cudaFuncAttributeMaxDynamicSharedMemorySize,
                         REC_SMEM_BYTES);
    cudaFuncSetAttribute(proj_mma,
                         cudaFuncAttributeMaxDynamicSharedMemorySize,
                         PJ_SMEM_BYTES);

    dim3 pgrid(Hsz / 64, (Bsz * Tsz) / 128);   // (8, 256)

    // Layer 0
    proj_mma<<<pgrid, 256, PJ_SMEM_BYTES>>>(x, W_ih0, b_ih0, b_hh0, buf0, Fsz);
    reset_flags<<<1, 128>>>();
    rnn_rec_mma<<<REC_NBLK, 256, REC_SMEM_BYTES>>>(buf0, W_hh0);

    // Layer 1
    proj_mma<<<pgrid, 256, PJ_SMEM_BYTES>>>(buf0, W_ih1, b_ih1, b_hh1, buf1, Hsz);
    reset_flags<<<1, 128>>>();
    rnn_rec_mma<<<REC_NBLK, 256, REC_SMEM_BYTES>>>(buf1, W_hh1);

    // Classifier
    fc_kernel<<<64, 256>>>(buf1, W_fc, b_fc, out);
}